// round 14
// baseline (speedup 1.0000x reference)
#include <cuda_runtime.h>
#include <cuda_bf16.h>
#include <math.h>
#include <stdint.h>

#define NWIN 512
#define NTOK 256
#define CH   96
#define NH   3
#define HD   32
#define HID  384
#define LDW  52    // stride (uint32) for 48-word operand rows (GEMM A/B, O_s)
#define LDV  20    // stride (uint32) for 16-word rows (K_s, V_s)
#define LOG2E 1.4426950408889634f

// Scratch (device globals)
__device__ float         g_t[(size_t)NWIN * NTOK * CH];       // residual fp32 [w][t][c]
__device__ __nv_bfloat16 g_q[(size_t)NWIN * NH * NTOK * HD];  // [t][d], pre-scaled by hd^-.5*log2e
__device__ __nv_bfloat16 g_k[(size_t)NWIN * NH * NTOK * HD];
__device__ __nv_bfloat16 g_v[(size_t)NWIN * NH * NTOK * HD];
// bias in per-thread C-fragment layout, bf16x2, *log2e
__device__ uint32_t g_biasb[3 * 16 * 4 * 32 * 16];
// weights as bf16x2 pairs
__device__ uint32_t gw_qkv[288 * 48];
__device__ uint32_t gw_proj[96 * 48];
__device__ uint32_t gw_fc1[384 * 48];
__device__ uint32_t gw_fc2[96 * 192];

// ---------------------------------------------------------------------------
__device__ __forceinline__ void cp_async16(void* s, const void* g) {
    uint32_t sa = (uint32_t)__cvta_generic_to_shared(s);
    asm volatile("cp.async.cg.shared.global [%0], [%1], 16;" :: "r"(sa), "l"(g));
}
#define CP_COMMIT asm volatile("cp.async.commit_group;")
#define CP_WAIT0  asm volatile("cp.async.wait_group 0;")

__device__ __forceinline__ uint32_t s2u(const void* p) {
    return (uint32_t)__cvta_generic_to_shared(p);
}
__device__ __forceinline__ uint32_t pk(float a, float b) {
    __nv_bfloat162 h = __floats2bfloat162_rn(a, b);
    return *(uint32_t*)&h;
}
__device__ __forceinline__ float2 upk(uint32_t u) {
    return __bfloat1622float2(*(const __nv_bfloat162*)&u);
}
__device__ __forceinline__ float ex2(float x) {
    float y;
    asm("ex2.approx.ftz.f32 %0, %1;" : "=f"(y) : "f"(x));
    return y;
}
// tanh-form GELU via ex2: gelu(v) = v*e/(e+1), e = exp2(v*(C1 + C2*v^2))
// C1 = 2*0.7978845608*log2e, C2 = C1*0.044715
__device__ __forceinline__ float gelu_f(float v) {
    const float C1 = 2.3022077594f;
    const float C2 = 0.1029432560f;
    float e = ex2(v * (C1 + C2 * v * v));
    return v * e / (e + 1.f);
}
__device__ __forceinline__ void bmma(float* c, const uint32_t* a, uint32_t b0, uint32_t b1) {
    asm("mma.sync.aligned.m16n8k16.row.col.f32.bf16.bf16.f32 "
        "{%0,%1,%2,%3},{%4,%5,%6,%7},{%8,%9},{%0,%1,%2,%3};"
        : "+f"(c[0]), "+f"(c[1]), "+f"(c[2]), "+f"(c[3])
        : "r"(a[0]), "r"(a[1]), "r"(a[2]), "r"(a[3]), "r"(b0), "r"(b1));
}
__device__ __forceinline__ void ldsm4(uint32_t* r, uint32_t a) {
    asm volatile("ldmatrix.sync.aligned.m8n8.x4.shared.b16 {%0,%1,%2,%3},[%4];"
        : "=r"(r[0]), "=r"(r[1]), "=r"(r[2]), "=r"(r[3]) : "r"(a));
}
__device__ __forceinline__ void ldsm4t(uint32_t* r, uint32_t a) {
    asm volatile("ldmatrix.sync.aligned.m8n8.x4.trans.shared.b16 {%0,%1,%2,%3},[%4];"
        : "=r"(r[0]), "=r"(r[1]), "=r"(r[2]), "=r"(r[3]) : "r"(a));
}

// 16 rows x NT*8 cols over KS*16 k; A from smem (stride LDW), B from smem.
template <int NT, int KS>
__device__ __forceinline__ void bgemm(const uint32_t* __restrict__ As,
                                      const uint32_t* __restrict__ Ws,
                                      float acc[NT][4], int tm, int l) {
    uint32_t aAddr = s2u(As) + ((tm + (l & 7) + ((l >> 3) & 1) * 8) * LDW + ((l >> 4) & 1) * 4) * 4;
    uint32_t bAddr = s2u(Ws) + (((l & 7) + ((l >> 4) & 1) * 8) * LDW + ((l >> 3) & 1) * 4) * 4;
    #pragma unroll
    for (int ks = 0; ks < KS; ks++) {
        uint32_t a[4];
        ldsm4(a, aAddr + ks * 32);
        #pragma unroll
        for (int nq = 0; nq < NT / 2; nq++) {
            uint32_t b[4];
            ldsm4(b, bAddr + (nq * 16 * LDW) * 4 + ks * 32);
            bmma(acc[2 * nq],     a, b[0], b[1]);
            bmma(acc[2 * nq + 1], a, b[2], b[3]);
        }
    }
}

// 32 rows (two 16-row tiles sharing B fragments) x NT*8 cols over KS*16 k.
template <int NT, int KS>
__device__ __forceinline__ void bgemm_dual(const uint32_t* __restrict__ As,
                                           const uint32_t* __restrict__ Ws,
                                           float accA[NT][4], float accB[NT][4],
                                           int tm, int l) {
    uint32_t aAddr = s2u(As) + ((tm + (l & 7) + ((l >> 3) & 1) * 8) * LDW + ((l >> 4) & 1) * 4) * 4;
    uint32_t bAddr = s2u(Ws) + (((l & 7) + ((l >> 4) & 1) * 8) * LDW + ((l >> 3) & 1) * 4) * 4;
    #pragma unroll
    for (int ks = 0; ks < KS; ks++) {
        uint32_t a0[4], a1[4];
        ldsm4(a0, aAddr + ks * 32);
        ldsm4(a1, aAddr + (16 * LDW) * 4 + ks * 32);
        #pragma unroll
        for (int nq = 0; nq < NT / 2; nq++) {
            uint32_t b[4];
            ldsm4(b, bAddr + (nq * 16 * LDW) * 4 + ks * 32);
            bmma(accA[2 * nq],     a0, b[0], b[1]);
            bmma(accA[2 * nq + 1], a0, b[2], b[3]);
            bmma(accB[2 * nq],     a1, b[0], b[1]);
            bmma(accB[2 * nq + 1], a1, b[2], b[3]);
        }
    }
}

// Same, but A fragments already in registers (pa[ks][4]).
template <int NT, int KS>
__device__ __forceinline__ void bgemm_ra(const uint32_t pa[][4],
                                         const uint32_t* __restrict__ Ws,
                                         float acc[NT][4], int l) {
    uint32_t bAddr = s2u(Ws) + (((l & 7) + ((l >> 4) & 1) * 8) * LDW + ((l >> 3) & 1) * 4) * 4;
    #pragma unroll
    for (int ks = 0; ks < KS; ks++) {
        #pragma unroll
        for (int nq = 0; nq < NT / 2; nq++) {
            uint32_t b[4];
            ldsm4(b, bAddr + (nq * 16 * LDW) * 4 + ks * 32);
            bmma(acc[2 * nq],     pa[ks], b[0], b[1]);
            bmma(acc[2 * nq + 1], pa[ks], b[2], b[3]);
        }
    }
}

// ---------------------------------------------------------------------------
// K0: fused prep (weights -> bf16x2) + bias gather (fragment layout)
// ---------------------------------------------------------------------------
__global__ void prep_kernel(const float* __restrict__ qkv_w, const float* __restrict__ proj_w,
                            const float* __restrict__ fc1_w, const float* __restrict__ fc2_w,
                            const float* __restrict__ bias_table) {
    if (blockIdx.x < 216) {
        int i = blockIdx.x * 256 + threadIdx.x;
        if (i < 13824) {
            int r = i / 48, p = i % 48;
            gw_qkv[i] = pk(qkv_w[r * 96 + 2 * p], qkv_w[r * 96 + 2 * p + 1]);
            return;
        }
        i -= 13824;
        if (i < 4608) {
            int r = i / 48, p = i % 48;
            gw_proj[i] = pk(proj_w[r * 96 + 2 * p], proj_w[r * 96 + 2 * p + 1]);
            return;
        }
        i -= 4608;
        if (i < 18432) {
            int r = i / 48, p = i % 48;
            gw_fc1[i] = pk(fc1_w[r * 96 + 2 * p], fc1_w[r * 96 + 2 * p + 1]);
            return;
        }
        i -= 18432;
        if (i < 18432) {
            int r = i / 192, p = i % 192;
            gw_fc2[i] = pk(fc2_w[r * 384 + 2 * p], fc2_w[r * 384 + 2 * p + 1]);
        }
        return;
    }
    int blk = blockIdx.x - 216;
    int j = blk & 3, rb = (blk >> 2) & 15, h = blk >> 6;
    int t = threadIdx.x;
    uint32_t* dst = g_biasb + blk * 512;
    #pragma unroll
    for (int q = 0; q < 2; q++) {
        int o = t * 2 + q;
        int l = o >> 4, wd = o & 15;
        int ni = wd >> 1, pp = wd & 1;
        float bv[2];
        #pragma unroll
        for (int e = 0; e < 2; e++) {
            int c = pp * 2 + e;
            int row = rb * 16 + (l >> 2) + ((c >> 1) << 3);
            int col = j * 64 + ni * 8 + 2 * (l & 3) + (c & 1);
            int dy = (col >> 4) - (row >> 4);
            int dx = (col & 15) - (row & 15);
            bv[e] = bias_table[((dy + 15) * 31 + (dx + 15)) * NH + h] * LOG2E;
        }
        dst[o] = pk(bv[0], bv[1]);
    }
}

// ---------------------------------------------------------------------------
// K1: window partition + LN1 + QKV GEMM, 128 tokens/CTA
// ---------------------------------------------------------------------------
__global__ __launch_bounds__(256, 2) void qkv_kernel(const float* __restrict__ x,
                                                     const float* __restrict__ qkv_b,
                                                     const float* __restrict__ ln_g,
                                                     const float* __restrict__ ln_b) {
    extern __shared__ uint32_t sm[];
    uint32_t* As  = sm;               // [128][LDW]
    uint32_t* Wb0 = sm + 128 * LDW;
    uint32_t* Wb1 = Wb0 + 96 * LDW;
    int bw = blockIdx.x, w = bw >> 1, half = bw & 1;
    int t = threadIdx.x, l = t & 31, wid = t >> 5, tm = wid * 16;
    int g = l >> 2, tg = l & 3;
    int b = w >> 8, hb = (w >> 4) & 15, wb = w & 15;

    for (int idx = t; idx < 96 * 12; idx += 256) {
        int r = idx / 12, c4 = idx % 12;
        cp_async16(&Wb0[r * LDW + c4 * 4], &gw_qkv[r * 48 + c4 * 4]);
    }
    CP_COMMIT;

    if (t < 128) {
        int tok = half * 128 + t;
        int d = tok >> 6, ii = (tok >> 3) & 7, jj = tok & 7;
        const float* xp = x + ((size_t)b * CH * 4 + d) * 16384 + (hb * 8 + ii) * 128 + (wb * 8 + jj);
        float row[96];
        float sum = 0.f, sq = 0.f;
        float* gt = g_t + ((size_t)w * NTOK + tok) * CH;
        #pragma unroll 4
        for (int c = 0; c < CH; c++) {
            float v = xp[(size_t)c * 65536];
            sum += v; sq += v * v;
            row[c] = v;
            gt[c] = v;
        }
        float mean = sum * (1.f / CH);
        float rstd = rsqrtf(sq * (1.f / CH) - mean * mean + 1e-5f);
        #pragma unroll
        for (int p = 0; p < 48; p++) {
            float n0 = (row[2*p]   - mean) * rstd * __ldg(ln_g + 2*p)   + __ldg(ln_b + 2*p);
            float n1 = (row[2*p+1] - mean) * rstd * __ldg(ln_g + 2*p+1) + __ldg(ln_b + 2*p+1);
            As[t * LDW + p] = pk(n0, n1);
        }
    }

    const float QS = 0.17677669529663687f * LOG2E;
    for (int chunk = 0; chunk < 3; chunk++) {
        uint32_t* Wc = (chunk & 1) ? Wb1 : Wb0;
        uint32_t* Wn = (chunk & 1) ? Wb0 : Wb1;
        CP_WAIT0;
        __syncthreads();
        if (chunk < 2) {
            for (int idx = t; idx < 96 * 12; idx += 256) {
                int r = idx / 12, c4 = idx % 12;
                cp_async16(&Wn[r * LDW + c4 * 4], &gw_qkv[((chunk + 1) * 96 + r) * 48 + c4 * 4]);
            }
            CP_COMMIT;
        }
        float acc[12][4];
        #pragma unroll
        for (int ni = 0; ni < 12; ni++)
            acc[ni][0] = acc[ni][1] = acc[ni][2] = acc[ni][3] = 0.f;
        bgemm<12, 6>(As, Wc, acc, tm, l);

        #pragma unroll
        for (int ni = 0; ni < 12; ni++) {
            int cn = ni * 8 + 2 * tg;
            int h = cn >> 5, dd = cn & 31;
            float b0v = qkv_b[chunk * CH + cn], b1v = qkv_b[chunk * CH + cn + 1];
            size_t base = ((size_t)(w * NH + h)) * NTOK;
            #pragma unroll
            for (int p = 0; p < 2; p++) {
                int row = half * 128 + tm + p * 8 + g;
                float v0 = acc[ni][2*p]   + b0v;
                float v1 = acc[ni][2*p+1] + b1v;
                uint32_t* dst = (chunk == 0) ? (uint32_t*)g_q
                              : (chunk == 1) ? (uint32_t*)g_k : (uint32_t*)g_v;
                float sc = (chunk == 0) ? QS : 1.f;
                dst[(base + row) * 16 + (dd >> 1)] = pk(v0 * sc, v1 * sc);
            }
        }
    }
}

// ---------------------------------------------------------------------------
// K2: fused attention (3 heads) + proj + residual; ONE CTA per window.
// ---------------------------------------------------------------------------
__global__ __launch_bounds__(256, 2) void attn_kernel(const float* __restrict__ proj_b) {
    extern __shared__ uint32_t smu[];
    uint32_t* O_s = smu;              // 13312
    uint32_t* K_s = smu + 13312;      // 5120
    uint32_t* V_s = smu + 18432;      // 5120
    uint32_t* Ws  = smu + 13312;      // overlay (proj)
    int w = blockIdx.x;
    int t = threadIdx.x, l = t & 31, wid = t >> 5, tm = wid * 32;
    int g = l >> 2, tg = l & 3;

    uint32_t kAddr = s2u(K_s) + (((l & 7) + ((l >> 4) & 1) * 8) * LDV + ((l >> 3) & 1) * 4) * 4;
    uint32_t vAddr = s2u(V_s) + (((l & 7) + ((l >> 3) & 1) * 8) * LDV + ((l >> 4) & 1) * 4) * 4;

    for (int h = 0; h < NH; h++) {
        size_t hbo = ((size_t)(w * NH + h)) * NTOK * HD;

        __syncthreads();
        for (int idx = t; idx < 2048; idx += 256) {
            int m = (idx & 1023) >> 2, c = idx & 3;
            const __nv_bfloat16* src = (idx < 1024) ? g_k : g_v;
            uint32_t* dst = (idx < 1024) ? K_s : V_s;
            cp_async16(&dst[m * LDV + c * 4], &src[hbo + m * 32 + c * 8]);
        }
        CP_COMMIT;

        uint32_t qa[2][2][4];
        {
            const uint32_t* qp = (const uint32_t*)(g_q + hbo);
            #pragma unroll
            for (int mi = 0; mi < 2; mi++) {
                int qrow = tm + mi * 16 + g;
                #pragma unroll
                for (int ks = 0; ks < 2; ks++) {
                    qa[mi][ks][0] = qp[qrow * 16 + 8 * ks + tg];
                    qa[mi][ks][1] = qp[(qrow + 8) * 16 + 8 * ks + tg];
                    qa[mi][ks][2] = qp[qrow * 16 + 8 * ks + tg + 4];
                    qa[mi][ks][3] = qp[(qrow + 8) * 16 + 8 * ks + tg + 4];
                }
            }
        }
        CP_WAIT0;
        __syncthreads();

        float l_r[2][2] = {{0.f, 0.f}, {0.f, 0.f}};
        float o[2][4][4];
        #pragma unroll
        for (int mi = 0; mi < 2; mi++)
            #pragma unroll
            for (int ni = 0; ni < 4; ni++)
                o[mi][ni][0] = o[mi][ni][1] = o[mi][ni][2] = o[mi][ni][3] = 0.f;

        for (int j = 0; j < 4; j++) {
            float s[2][8][4];
            #pragma unroll
            for (int mi = 0; mi < 2; mi++) {
                const uint4* bf = (const uint4*)(g_biasb +
                    (((h * 16 + wid * 2 + mi) * 4 + j) << 9) + l * 16);
                uint4 u0 = bf[0], u1 = bf[1], u2 = bf[2], u3 = bf[3];
                uint32_t wds[16] = {u0.x, u0.y, u0.z, u0.w, u1.x, u1.y, u1.z, u1.w,
                                    u2.x, u2.y, u2.z, u2.w, u3.x, u3.y, u3.z, u3.w};
                #pragma unroll
                for (int ni = 0; ni < 8; ni++) {
                    float2 a = upk(wds[2 * ni]);
                    float2 b = upk(wds[2 * ni + 1]);
                    s[mi][ni][0] = a.x; s[mi][ni][1] = a.y;
                    s[mi][ni][2] = b.x; s[mi][ni][3] = b.y;
                }
            }
            #pragma unroll
            for (int np = 0; np < 4; np++)
                #pragma unroll
                for (int ks = 0; ks < 2; ks++) {
                    uint32_t bq[4];
                    ldsm4(bq, kAddr + ((j * 64 + np * 16) * LDV + ks * 8) * 4);
                    #pragma unroll
                    for (int mi = 0; mi < 2; mi++) {
                        bmma(s[mi][2 * np],     qa[mi][ks], bq[0], bq[1]);
                        bmma(s[mi][2 * np + 1], qa[mi][ks], bq[2], bq[3]);
                    }
                }
            #pragma unroll
            for (int mi = 0; mi < 2; mi++)
                #pragma unroll
                for (int ni = 0; ni < 8; ni++) {
                    s[mi][ni][0] = ex2(s[mi][ni][0]);
                    s[mi][ni][1] = ex2(s[mi][ni][1]);
                    s[mi][ni][2] = ex2(s[mi][ni][2]);
                    s[mi][ni][3] = ex2(s[mi][ni][3]);
                    l_r[mi][0] += s[mi][ni][0] + s[mi][ni][1];
                    l_r[mi][1] += s[mi][ni][2] + s[mi][ni][3];
                }
            uint32_t pa[2][4][4];
            #pragma unroll
            for (int mi = 0; mi < 2; mi++)
                #pragma unroll
                for (int ks = 0; ks < 4; ks++) {
                    pa[mi][ks][0] = pk(s[mi][2*ks][0],   s[mi][2*ks][1]);
                    pa[mi][ks][1] = pk(s[mi][2*ks][2],   s[mi][2*ks][3]);
                    pa[mi][ks][2] = pk(s[mi][2*ks+1][0], s[mi][2*ks+1][1]);
                    pa[mi][ks][3] = pk(s[mi][2*ks+1][2], s[mi][2*ks+1][3]);
                }
            #pragma unroll
            for (int ks = 0; ks < 4; ks++)
                #pragma unroll
                for (int nq = 0; nq < 2; nq++) {
                    uint32_t bv[4];
                    ldsm4t(bv, vAddr + ((j * 64 + ks * 16) * LDV + nq * 8) * 4);
                    #pragma unroll
                    for (int mi = 0; mi < 2; mi++) {
                        bmma(o[mi][2 * nq],     pa[mi][ks], bv[0], bv[1]);
                        bmma(o[mi][2 * nq + 1], pa[mi][ks], bv[2], bv[3]);
                    }
                }
        }
        #pragma unroll
        for (int mi = 0; mi < 2; mi++)
            #pragma unroll
            for (int p = 0; p < 2; p++) {
                l_r[mi][p] += __shfl_xor_sync(0xffffffffu, l_r[mi][p], 1);
                l_r[mi][p] += __shfl_xor_sync(0xffffffffu, l_r[mi][p], 2);
            }
        #pragma unroll
        for (int mi = 0; mi < 2; mi++) {
            float rinv[2] = {1.f / l_r[mi][0], 1.f / l_r[mi][1]};
            #pragma unroll
            for (int p = 0; p < 2; p++) {
                int rloc = tm + mi * 16 + p * 8 + g;
                #pragma unroll
                for (int ni = 0; ni < 4; ni++)
                    O_s[rloc * LDW + h * 16 + ni * 4 + tg] =
                        pk(o[mi][ni][2*p] * rinv[p], o[mi][ni][2*p+1] * rinv[p]);
            }
        }
    }

    // ---- proj + residual ----
    __syncthreads();
    for (int idx = t; idx < 96 * 12; idx += 256) {
        int r = idx / 12, c4 = idx % 12;
        cp_async16(&Ws[r * LDW + c4 * 4], &gw_proj[r * 48 + c4 * 4]);
    }
    CP_COMMIT;
    CP_WAIT0;
    __syncthreads();

    float accA[12][4], accB[12][4];
    #pragma unroll
    for (int ni = 0; ni < 12; ni++) {
        accA[ni][0] = accA[ni][1] = accA[ni][2] = accA[ni][3] = 0.f;
        accB[ni][0] = accB[ni][1] = accB[ni][2] = accB[ni][3] = 0.f;
    }
    bgemm_dual<12, 6>(O_s, Ws, accA, accB, tm, l);

    #pragma unroll
    for (int ni = 0; ni < 12; ni++) {
        int cn = ni * 8 + 2 * tg;
        float b0v = proj_b[cn], b1v = proj_b[cn + 1];
        #pragma unroll
        for (int p = 0; p < 2; p++) {
            int rowA = tm + p * 8 + g;
            int rowB = tm + 16 + p * 8 + g;
            float* tA = &g_t[((size_t)w * NTOK + rowA) * CH + cn];
            float* tB = &g_t[((size_t)w * NTOK + rowB) * CH + cn];
            float2 pA = *(float2*)tA, pB = *(float2*)tB;
            pA.x += accA[ni][2*p] + b0v;  pA.y += accA[ni][2*p+1] + b1v;
            pB.x += accB[ni][2*p] + b0v;  pB.y += accB[ni][2*p+1] + b1v;
            *(float2*)tA = pA; *(float2*)tB = pB;
        }
    }
}

// ---------------------------------------------------------------------------
// K3: fused MLP: LN2 + fc1 + tanh-GELU(regs) + fc2 + residual, 128 tokens/CTA
// ---------------------------------------------------------------------------
__global__ __launch_bounds__(256, 2) void mlp_kernel(const float* __restrict__ ln_g,
                                                     const float* __restrict__ ln_b,
                                                     const float* __restrict__ fc1_b,
                                                     const float* __restrict__ fc2_b,
                                                     float* __restrict__ out) {
    extern __shared__ uint32_t sm[];
    uint32_t* As = sm;                                  // 6656
    uint32_t* W1[2] = {sm + 6656,              sm + 6656 + 4992};
    uint32_t* W2[2] = {sm + 6656 + 2 * 4992,   sm + 6656 + 3 * 4992};
    int bw = blockIdx.x, w = bw >> 1, half = bw & 1;
    int t = threadIdx.x, l = t & 31, wid = t >> 5, tm = wid * 16;
    int g = l >> 2, tg = l & 3;

    for (int idx = t; idx < 96 * 12; idx += 256) {
        int r = idx / 12, c4 = idx % 12;
        cp_async16(&W1[0][r * LDW + c4 * 4], &gw_fc1[r * 48 + c4 * 4]);
        cp_async16(&W2[0][r * LDW + c4 * 4], &gw_fc2[r * 192 + c4 * 4]);
    }
    CP_COMMIT;

    if (t < 128) {
        int tok = half * 128 + t;
        const float4* tp = (const float4*)(g_t + ((size_t)w * NTOK + tok) * CH);
        float row[96];
        float sum = 0.f, sq = 0.f;
        #pragma unroll
        for (int c4 = 0; c4 < 24; c4++) {
            float4 v = tp[c4];
            row[4*c4] = v.x; row[4*c4+1] = v.y; row[4*c4+2] = v.z; row[4*c4+3] = v.w;
            sum += v.x + v.y + v.z + v.w;
            sq  += v.x*v.x + v.y*v.y + v.z*v.z + v.w*v.w;
        }
        float mean = sum * (1.f / CH);
        float rstd = rsqrtf(sq * (1.f / CH) - mean * mean + 1e-5f);
        #pragma unroll
        for (int p = 0; p < 48; p++) {
            float n0 = (row[2*p]   - mean) * rstd * __ldg(ln_g + 2*p)   + __ldg(ln_b + 2*p);
            float n1 = (row[2*p+1] - mean) * rstd * __ldg(ln_g + 2*p+1) + __ldg(ln_b + 2*p+1);
            As[t * LDW + p] = pk(n0, n1);
        }
    }

    float acc2[12][4];
    #pragma unroll
    for (int ni = 0; ni < 12; ni++)
        acc2[ni][0] = acc2[ni][1] = acc2[ni][2] = acc2[ni][3] = 0.f;

    for (int c = 0; c < 4; c++) {
        int cur = c & 1, nxt = cur ^ 1;
        CP_WAIT0;
        __syncthreads();
        if (c < 3) {
            for (int idx = t; idx < 96 * 12; idx += 256) {
                int r = idx / 12, c4 = idx % 12;
                cp_async16(&W1[nxt][r * LDW + c4 * 4], &gw_fc1[((c + 1) * 96 + r) * 48 + c4 * 4]);
                cp_async16(&W2[nxt][r * LDW + c4 * 4], &gw_fc2[r * 192 + (c + 1) * 48 + c4 * 4]);
            }
            CP_COMMIT;
        }

        float acc1[12][4];
        #pragma unroll
        for (int ni = 0; ni < 12; ni++)
            acc1[ni][0] = acc1[ni][1] = acc1[ni][2] = acc1[ni][3] = 0.f;
        bgemm<12, 6>(As, W1[cur], acc1, tm, l);

        uint32_t pa[6][4];
        #pragma unroll
        for (int ni = 0; ni < 12; ni++) {
            int cn = ni * 8 + 2 * tg;
            float b0v = fc1_b[c * CH + cn], b1v = fc1_b[c * CH + cn + 1];
            acc1[ni][0] = gelu_f(acc1[ni][0] + b0v);
            acc1[ni][1] = gelu_f(acc1[ni][1] + b1v);
            acc1[ni][2] = gelu_f(acc1[ni][2] + b0v);
            acc1[ni][3] = gelu_f(acc1[ni][3] + b1v);
        }
        #pragma unroll
        for (int ks = 0; ks < 6; ks++) {
            pa[ks][0] = pk(acc1[2*ks][0],   acc1[2*ks][1]);
            pa[ks][1] = pk(acc1[2*ks][2],   acc1[2*ks][3]);
            pa[ks][2] = pk(acc1[2*ks+1][0], acc1[2*ks+1][1]);
            pa[ks][3] = pk(acc1[2*ks+1][2], acc1[2*ks+1][3]);
        }
        bgemm_ra<12, 6>(pa, W2[cur], acc2, l);
    }

    #pragma unroll
    for (int ni = 0; ni < 12; ni++) {
        int cn = ni * 8 + 2 * tg;
        float b0v = fc2_b[cn], b1v = fc2_b[cn + 1];
        #pragma unroll
        for (int p = 0; p < 2; p++) {
            int row = half * 128 + tm + p * 8 + g;
            const float2 tr = *(const float2*)&g_t[((size_t)w * NTOK + row) * CH + cn];
            float2 v = make_float2(acc2[ni][2*p]   + b0v + tr.x,
                                   acc2[ni][2*p+1] + b1v + tr.y);
            *(float2*)&out[((size_t)w * NTOK + row) * CH + cn] = v;
        }
    }
}

// ---------------------------------------------------------------------------
extern "C" void kernel_launch(void* const* d_in, const int* in_sizes, int n_in,
                              void* d_out, int out_size) {
    (void)in_sizes; (void)n_in; (void)out_size;
    const float* x      = (const float*)d_in[0];
    const float* qkv_w  = (const float*)d_in[1];
    const float* qkv_b  = (const float*)d_in[2];
    const float* proj_w = (const float*)d_in[3];
    const float* proj_b = (const float*)d_in[4];
    const float* btab   = (const float*)d_in[5];
    const float* ln1_g  = (const float*)d_in[6];
    const float* ln1_b  = (const float*)d_in[7];
    const float* ln2_g  = (const float*)d_in[8];
    const float* ln2_b  = (const float*)d_in[9];
    const float* fc1_w  = (const float*)d_in[10];
    const float* fc1_b  = (const float*)d_in[11];
    const float* fc2_w  = (const float*)d_in[12];
    const float* fc2_b  = (const float*)d_in[13];
    float* out = (float*)d_out;

    const int smem_qkv  = (128 * LDW + 2 * 96 * LDW) * 4;    // 66560 B
    const int smem_attn = (13312 + 5120 + 5120) * 4;         // 94208 B
    const int smem_mlp  = (6656 + 4 * 4992) * 4;             // 106496 B
    cudaFuncSetAttribute(qkv_kernel,  cudaFuncAttributeMaxDynamicSharedMemorySize, smem_qkv);
    cudaFuncSetAttribute(attn_kernel, cudaFuncAttributeMaxDynamicSharedMemorySize, smem_attn);
    cudaFuncSetAttribute(mlp_kernel,  cudaFuncAttributeMaxDynamicSharedMemorySize, smem_mlp);

    prep_kernel<<<408, 256>>>(qkv_w, proj_w, fc1_w, fc2_w, btab);
    qkv_kernel<<<NWIN * 2, 256, smem_qkv>>>(x, qkv_b, ln1_g, ln1_b);
    attn_kernel<<<NWIN, 256, smem_attn>>>(proj_b);
    mlp_kernel<<<NWIN * 2, 256, smem_mlp>>>(ln2_g, ln2_b, fc1_b, fc2_b, out);
}

// round 15
// speedup vs baseline: 1.2141x; 1.2141x over previous
#include <cuda_runtime.h>
#include <cuda_bf16.h>
#include <math.h>
#include <stdint.h>

#define NWIN 512
#define NTOK 256
#define CH   96
#define NH   3
#define HD   32
#define HID  384
#define LDW  52    // stride (uint32) for 48-word operand rows (GEMM A/B, O_s)
#define LDV  20    // stride (uint32) for 16-word rows (K_s, V_s)
#define LOG2E 1.4426950408889634f

// Scratch (device globals)
__device__ float         g_t[(size_t)NWIN * NTOK * CH];       // residual fp32 [w][t][c]
__device__ __nv_bfloat16 g_q[(size_t)NWIN * NH * NTOK * HD];  // [t][d], pre-scaled by hd^-.5*log2e
__device__ __nv_bfloat16 g_k[(size_t)NWIN * NH * NTOK * HD];
__device__ __nv_bfloat16 g_v[(size_t)NWIN * NH * NTOK * HD];
// bias in per-thread C-fragment layout, bf16x2, *log2e
__device__ uint32_t g_biasb[3 * 16 * 4 * 32 * 16];
// weights as bf16x2 pairs
__device__ uint32_t gw_qkv[288 * 48];
__device__ uint32_t gw_proj[96 * 48];
__device__ uint32_t gw_fc1[384 * 48];
__device__ uint32_t gw_fc2[96 * 192];

// ---------------------------------------------------------------------------
__device__ __forceinline__ void cp_async16(void* s, const void* g) {
    uint32_t sa = (uint32_t)__cvta_generic_to_shared(s);
    asm volatile("cp.async.cg.shared.global [%0], [%1], 16;" :: "r"(sa), "l"(g));
}
#define CP_COMMIT asm volatile("cp.async.commit_group;")
#define CP_WAIT0  asm volatile("cp.async.wait_group 0;")

__device__ __forceinline__ uint32_t s2u(const void* p) {
    return (uint32_t)__cvta_generic_to_shared(p);
}
__device__ __forceinline__ uint32_t pk(float a, float b) {
    __nv_bfloat162 h = __floats2bfloat162_rn(a, b);
    return *(uint32_t*)&h;
}
__device__ __forceinline__ float2 upk(uint32_t u) {
    return __bfloat1622float2(*(const __nv_bfloat162*)&u);
}
__device__ __forceinline__ float ex2(float x) {
    float y;
    asm("ex2.approx.ftz.f32 %0, %1;" : "=f"(y) : "f"(x));
    return y;
}
// tanh-form GELU via HW tanh.approx (1 MUFU + ~4 FFMA per value)
__device__ __forceinline__ float gelu_f(float v) {
    float u = v * (0.7978845608f + 0.0356774081f * v * v);
    float th;
    asm("tanh.approx.f32 %0, %1;" : "=f"(th) : "f"(u));
    return 0.5f * v * (1.f + th);
}
__device__ __forceinline__ void bmma(float* c, const uint32_t* a, uint32_t b0, uint32_t b1) {
    asm("mma.sync.aligned.m16n8k16.row.col.f32.bf16.bf16.f32 "
        "{%0,%1,%2,%3},{%4,%5,%6,%7},{%8,%9},{%0,%1,%2,%3};"
        : "+f"(c[0]), "+f"(c[1]), "+f"(c[2]), "+f"(c[3])
        : "r"(a[0]), "r"(a[1]), "r"(a[2]), "r"(a[3]), "r"(b0), "r"(b1));
}
__device__ __forceinline__ void ldsm4(uint32_t* r, uint32_t a) {
    asm volatile("ldmatrix.sync.aligned.m8n8.x4.shared.b16 {%0,%1,%2,%3},[%4];"
        : "=r"(r[0]), "=r"(r[1]), "=r"(r[2]), "=r"(r[3]) : "r"(a));
}
__device__ __forceinline__ void ldsm4t(uint32_t* r, uint32_t a) {
    asm volatile("ldmatrix.sync.aligned.m8n8.x4.trans.shared.b16 {%0,%1,%2,%3},[%4];"
        : "=r"(r[0]), "=r"(r[1]), "=r"(r[2]), "=r"(r[3]) : "r"(a));
}

// 16 rows x NT*8 cols over KS*16 k; A from smem (stride LDW), B from smem.
template <int NT, int KS>
__device__ __forceinline__ void bgemm(const uint32_t* __restrict__ As,
                                      const uint32_t* __restrict__ Ws,
                                      float acc[NT][4], int tm, int l) {
    uint32_t aAddr = s2u(As) + ((tm + (l & 7) + ((l >> 3) & 1) * 8) * LDW + ((l >> 4) & 1) * 4) * 4;
    uint32_t bAddr = s2u(Ws) + (((l & 7) + ((l >> 4) & 1) * 8) * LDW + ((l >> 3) & 1) * 4) * 4;
    #pragma unroll
    for (int ks = 0; ks < KS; ks++) {
        uint32_t a[4];
        ldsm4(a, aAddr + ks * 32);
        #pragma unroll
        for (int nq = 0; nq < NT / 2; nq++) {
            uint32_t b[4];
            ldsm4(b, bAddr + (nq * 16 * LDW) * 4 + ks * 32);
            bmma(acc[2 * nq],     a, b[0], b[1]);
            bmma(acc[2 * nq + 1], a, b[2], b[3]);
        }
    }
}

// 32 rows (two 16-row tiles sharing B fragments) x NT*8 cols over KS*16 k.
template <int NT, int KS>
__device__ __forceinline__ void bgemm_dual(const uint32_t* __restrict__ As,
                                           const uint32_t* __restrict__ Ws,
                                           float accA[NT][4], float accB[NT][4],
                                           int tm, int l) {
    uint32_t aAddr = s2u(As) + ((tm + (l & 7) + ((l >> 3) & 1) * 8) * LDW + ((l >> 4) & 1) * 4) * 4;
    uint32_t bAddr = s2u(Ws) + (((l & 7) + ((l >> 4) & 1) * 8) * LDW + ((l >> 3) & 1) * 4) * 4;
    #pragma unroll
    for (int ks = 0; ks < KS; ks++) {
        uint32_t a0[4], a1[4];
        ldsm4(a0, aAddr + ks * 32);
        ldsm4(a1, aAddr + (16 * LDW) * 4 + ks * 32);
        #pragma unroll
        for (int nq = 0; nq < NT / 2; nq++) {
            uint32_t b[4];
            ldsm4(b, bAddr + (nq * 16 * LDW) * 4 + ks * 32);
            bmma(accA[2 * nq],     a0, b[0], b[1]);
            bmma(accA[2 * nq + 1], a0, b[2], b[3]);
            bmma(accB[2 * nq],     a1, b[0], b[1]);
            bmma(accB[2 * nq + 1], a1, b[2], b[3]);
        }
    }
}

// Same, but A fragments already in registers (pa[ks][4]).
template <int NT, int KS>
__device__ __forceinline__ void bgemm_ra(const uint32_t pa[][4],
                                         const uint32_t* __restrict__ Ws,
                                         float acc[NT][4], int l) {
    uint32_t bAddr = s2u(Ws) + (((l & 7) + ((l >> 4) & 1) * 8) * LDW + ((l >> 3) & 1) * 4) * 4;
    #pragma unroll
    for (int ks = 0; ks < KS; ks++) {
        #pragma unroll
        for (int nq = 0; nq < NT / 2; nq++) {
            uint32_t b[4];
            ldsm4(b, bAddr + (nq * 16 * LDW) * 4 + ks * 32);
            bmma(acc[2 * nq],     pa[ks], b[0], b[1]);
            bmma(acc[2 * nq + 1], pa[ks], b[2], b[3]);
        }
    }
}

// ---------------------------------------------------------------------------
// K0: fused prep (weights -> bf16x2) + bias gather (fragment layout)
// ---------------------------------------------------------------------------
__global__ void prep_kernel(const float* __restrict__ qkv_w, const float* __restrict__ proj_w,
                            const float* __restrict__ fc1_w, const float* __restrict__ fc2_w,
                            const float* __restrict__ bias_table) {
    if (blockIdx.x < 216) {
        int i = blockIdx.x * 256 + threadIdx.x;
        if (i < 13824) {
            int r = i / 48, p = i % 48;
            gw_qkv[i] = pk(qkv_w[r * 96 + 2 * p], qkv_w[r * 96 + 2 * p + 1]);
            return;
        }
        i -= 13824;
        if (i < 4608) {
            int r = i / 48, p = i % 48;
            gw_proj[i] = pk(proj_w[r * 96 + 2 * p], proj_w[r * 96 + 2 * p + 1]);
            return;
        }
        i -= 4608;
        if (i < 18432) {
            int r = i / 48, p = i % 48;
            gw_fc1[i] = pk(fc1_w[r * 96 + 2 * p], fc1_w[r * 96 + 2 * p + 1]);
            return;
        }
        i -= 18432;
        if (i < 18432) {
            int r = i / 192, p = i % 192;
            gw_fc2[i] = pk(fc2_w[r * 384 + 2 * p], fc2_w[r * 384 + 2 * p + 1]);
        }
        return;
    }
    int blk = blockIdx.x - 216;
    int j = blk & 3, rb = (blk >> 2) & 15, h = blk >> 6;
    int t = threadIdx.x;
    uint32_t* dst = g_biasb + blk * 512;
    #pragma unroll
    for (int q = 0; q < 2; q++) {
        int o = t * 2 + q;
        int l = o >> 4, wd = o & 15;
        int ni = wd >> 1, pp = wd & 1;
        float bv[2];
        #pragma unroll
        for (int e = 0; e < 2; e++) {
            int c = pp * 2 + e;
            int row = rb * 16 + (l >> 2) + ((c >> 1) << 3);
            int col = j * 64 + ni * 8 + 2 * (l & 3) + (c & 1);
            int dy = (col >> 4) - (row >> 4);
            int dx = (col & 15) - (row & 15);
            bv[e] = bias_table[((dy + 15) * 31 + (dx + 15)) * NH + h] * LOG2E;
        }
        dst[o] = pk(bv[0], bv[1]);
    }
}

// ---------------------------------------------------------------------------
// K1: window partition + LN1 + QKV GEMM, 128 tokens/CTA
// ---------------------------------------------------------------------------
__global__ __launch_bounds__(256, 2) void qkv_kernel(const float* __restrict__ x,
                                                     const float* __restrict__ qkv_b,
                                                     const float* __restrict__ ln_g,
                                                     const float* __restrict__ ln_b) {
    extern __shared__ uint32_t sm[];
    uint32_t* As  = sm;               // [128][LDW]
    uint32_t* Wb0 = sm + 128 * LDW;
    uint32_t* Wb1 = Wb0 + 96 * LDW;
    int bw = blockIdx.x, w = bw >> 1, half = bw & 1;
    int t = threadIdx.x, l = t & 31, wid = t >> 5, tm = wid * 16;
    int g = l >> 2, tg = l & 3;
    int b = w >> 8, hb = (w >> 4) & 15, wb = w & 15;

    for (int idx = t; idx < 96 * 12; idx += 256) {
        int r = idx / 12, c4 = idx % 12;
        cp_async16(&Wb0[r * LDW + c4 * 4], &gw_qkv[r * 48 + c4 * 4]);
    }
    CP_COMMIT;

    if (t < 128) {
        int tok = half * 128 + t;
        int d = tok >> 6, ii = (tok >> 3) & 7, jj = tok & 7;
        const float* xp = x + ((size_t)b * CH * 4 + d) * 16384 + (hb * 8 + ii) * 128 + (wb * 8 + jj);
        float row[96];
        float sum = 0.f, sq = 0.f;
        float* gt = g_t + ((size_t)w * NTOK + tok) * CH;
        #pragma unroll 4
        for (int c = 0; c < CH; c++) {
            float v = xp[(size_t)c * 65536];
            sum += v; sq += v * v;
            row[c] = v;
            gt[c] = v;
        }
        float mean = sum * (1.f / CH);
        float rstd = rsqrtf(sq * (1.f / CH) - mean * mean + 1e-5f);
        #pragma unroll
        for (int p = 0; p < 48; p++) {
            float n0 = (row[2*p]   - mean) * rstd * __ldg(ln_g + 2*p)   + __ldg(ln_b + 2*p);
            float n1 = (row[2*p+1] - mean) * rstd * __ldg(ln_g + 2*p+1) + __ldg(ln_b + 2*p+1);
            As[t * LDW + p] = pk(n0, n1);
        }
    }

    const float QS = 0.17677669529663687f * LOG2E;
    for (int chunk = 0; chunk < 3; chunk++) {
        uint32_t* Wc = (chunk & 1) ? Wb1 : Wb0;
        uint32_t* Wn = (chunk & 1) ? Wb0 : Wb1;
        CP_WAIT0;
        __syncthreads();
        if (chunk < 2) {
            for (int idx = t; idx < 96 * 12; idx += 256) {
                int r = idx / 12, c4 = idx % 12;
                cp_async16(&Wn[r * LDW + c4 * 4], &gw_qkv[((chunk + 1) * 96 + r) * 48 + c4 * 4]);
            }
            CP_COMMIT;
        }
        float acc[12][4];
        #pragma unroll
        for (int ni = 0; ni < 12; ni++)
            acc[ni][0] = acc[ni][1] = acc[ni][2] = acc[ni][3] = 0.f;
        bgemm<12, 6>(As, Wc, acc, tm, l);

        #pragma unroll
        for (int ni = 0; ni < 12; ni++) {
            int cn = ni * 8 + 2 * tg;
            int h = cn >> 5, dd = cn & 31;
            float b0v = qkv_b[chunk * CH + cn], b1v = qkv_b[chunk * CH + cn + 1];
            size_t base = ((size_t)(w * NH + h)) * NTOK;
            #pragma unroll
            for (int p = 0; p < 2; p++) {
                int row = half * 128 + tm + p * 8 + g;
                float v0 = acc[ni][2*p]   + b0v;
                float v1 = acc[ni][2*p+1] + b1v;
                uint32_t* dst = (chunk == 0) ? (uint32_t*)g_q
                              : (chunk == 1) ? (uint32_t*)g_k : (uint32_t*)g_v;
                float sc = (chunk == 0) ? QS : 1.f;
                dst[(base + row) * 16 + (dd >> 1)] = pk(v0 * sc, v1 * sc);
            }
        }
    }
}

// ---------------------------------------------------------------------------
// K2: fused attention (3 heads) + proj + residual; ONE CTA per window.
// ---------------------------------------------------------------------------
__global__ __launch_bounds__(256, 2) void attn_kernel(const float* __restrict__ proj_b) {
    extern __shared__ uint32_t smu[];
    uint32_t* O_s = smu;              // 13312
    uint32_t* K_s = smu + 13312;      // 5120
    uint32_t* V_s = smu + 18432;      // 5120
    uint32_t* Ws  = smu + 13312;      // overlay (proj)
    int w = blockIdx.x;
    int t = threadIdx.x, l = t & 31, wid = t >> 5, tm = wid * 32;
    int g = l >> 2, tg = l & 3;

    uint32_t kAddr = s2u(K_s) + (((l & 7) + ((l >> 4) & 1) * 8) * LDV + ((l >> 3) & 1) * 4) * 4;
    uint32_t vAddr = s2u(V_s) + (((l & 7) + ((l >> 3) & 1) * 8) * LDV + ((l >> 4) & 1) * 4) * 4;

    for (int h = 0; h < NH; h++) {
        size_t hbo = ((size_t)(w * NH + h)) * NTOK * HD;

        __syncthreads();
        for (int idx = t; idx < 2048; idx += 256) {
            int m = (idx & 1023) >> 2, c = idx & 3;
            const __nv_bfloat16* src = (idx < 1024) ? g_k : g_v;
            uint32_t* dst = (idx < 1024) ? K_s : V_s;
            cp_async16(&dst[m * LDV + c * 4], &src[hbo + m * 32 + c * 8]);
        }
        CP_COMMIT;

        uint32_t qa[2][2][4];
        {
            const uint32_t* qp = (const uint32_t*)(g_q + hbo);
            #pragma unroll
            for (int mi = 0; mi < 2; mi++) {
                int qrow = tm + mi * 16 + g;
                #pragma unroll
                for (int ks = 0; ks < 2; ks++) {
                    qa[mi][ks][0] = qp[qrow * 16 + 8 * ks + tg];
                    qa[mi][ks][1] = qp[(qrow + 8) * 16 + 8 * ks + tg];
                    qa[mi][ks][2] = qp[qrow * 16 + 8 * ks + tg + 4];
                    qa[mi][ks][3] = qp[(qrow + 8) * 16 + 8 * ks + tg + 4];
                }
            }
        }
        CP_WAIT0;
        __syncthreads();

        float l_r[2][2] = {{0.f, 0.f}, {0.f, 0.f}};
        float o[2][4][4];
        #pragma unroll
        for (int mi = 0; mi < 2; mi++)
            #pragma unroll
            for (int ni = 0; ni < 4; ni++)
                o[mi][ni][0] = o[mi][ni][1] = o[mi][ni][2] = o[mi][ni][3] = 0.f;

        for (int j = 0; j < 4; j++) {
            float s[2][8][4];
            #pragma unroll
            for (int mi = 0; mi < 2; mi++) {
                const uint4* bf = (const uint4*)(g_biasb +
                    (((h * 16 + wid * 2 + mi) * 4 + j) << 9) + l * 16);
                uint4 u0 = bf[0], u1 = bf[1], u2 = bf[2], u3 = bf[3];
                uint32_t wds[16] = {u0.x, u0.y, u0.z, u0.w, u1.x, u1.y, u1.z, u1.w,
                                    u2.x, u2.y, u2.z, u2.w, u3.x, u3.y, u3.z, u3.w};
                #pragma unroll
                for (int ni = 0; ni < 8; ni++) {
                    float2 a = upk(wds[2 * ni]);
                    float2 b = upk(wds[2 * ni + 1]);
                    s[mi][ni][0] = a.x; s[mi][ni][1] = a.y;
                    s[mi][ni][2] = b.x; s[mi][ni][3] = b.y;
                }
            }
            #pragma unroll
            for (int np = 0; np < 4; np++)
                #pragma unroll
                for (int ks = 0; ks < 2; ks++) {
                    uint32_t bq[4];
                    ldsm4(bq, kAddr + ((j * 64 + np * 16) * LDV + ks * 8) * 4);
                    #pragma unroll
                    for (int mi = 0; mi < 2; mi++) {
                        bmma(s[mi][2 * np],     qa[mi][ks], bq[0], bq[1]);
                        bmma(s[mi][2 * np + 1], qa[mi][ks], bq[2], bq[3]);
                    }
                }
            #pragma unroll
            for (int mi = 0; mi < 2; mi++)
                #pragma unroll
                for (int ni = 0; ni < 8; ni++) {
                    s[mi][ni][0] = ex2(s[mi][ni][0]);
                    s[mi][ni][1] = ex2(s[mi][ni][1]);
                    s[mi][ni][2] = ex2(s[mi][ni][2]);
                    s[mi][ni][3] = ex2(s[mi][ni][3]);
                    l_r[mi][0] += s[mi][ni][0] + s[mi][ni][1];
                    l_r[mi][1] += s[mi][ni][2] + s[mi][ni][3];
                }
            uint32_t pa[2][4][4];
            #pragma unroll
            for (int mi = 0; mi < 2; mi++)
                #pragma unroll
                for (int ks = 0; ks < 4; ks++) {
                    pa[mi][ks][0] = pk(s[mi][2*ks][0],   s[mi][2*ks][1]);
                    pa[mi][ks][1] = pk(s[mi][2*ks][2],   s[mi][2*ks][3]);
                    pa[mi][ks][2] = pk(s[mi][2*ks+1][0], s[mi][2*ks+1][1]);
                    pa[mi][ks][3] = pk(s[mi][2*ks+1][2], s[mi][2*ks+1][3]);
                }
            #pragma unroll
            for (int ks = 0; ks < 4; ks++)
                #pragma unroll
                for (int nq = 0; nq < 2; nq++) {
                    uint32_t bv[4];
                    ldsm4t(bv, vAddr + ((j * 64 + ks * 16) * LDV + nq * 8) * 4);
                    #pragma unroll
                    for (int mi = 0; mi < 2; mi++) {
                        bmma(o[mi][2 * nq],     pa[mi][ks], bv[0], bv[1]);
                        bmma(o[mi][2 * nq + 1], pa[mi][ks], bv[2], bv[3]);
                    }
                }
        }
        #pragma unroll
        for (int mi = 0; mi < 2; mi++)
            #pragma unroll
            for (int p = 0; p < 2; p++) {
                l_r[mi][p] += __shfl_xor_sync(0xffffffffu, l_r[mi][p], 1);
                l_r[mi][p] += __shfl_xor_sync(0xffffffffu, l_r[mi][p], 2);
            }
        #pragma unroll
        for (int mi = 0; mi < 2; mi++) {
            float rinv[2] = {1.f / l_r[mi][0], 1.f / l_r[mi][1]};
            #pragma unroll
            for (int p = 0; p < 2; p++) {
                int rloc = tm + mi * 16 + p * 8 + g;
                #pragma unroll
                for (int ni = 0; ni < 4; ni++)
                    O_s[rloc * LDW + h * 16 + ni * 4 + tg] =
                        pk(o[mi][ni][2*p] * rinv[p], o[mi][ni][2*p+1] * rinv[p]);
            }
        }
    }

    // ---- proj + residual ----
    __syncthreads();
    for (int idx = t; idx < 96 * 12; idx += 256) {
        int r = idx / 12, c4 = idx % 12;
        cp_async16(&Ws[r * LDW + c4 * 4], &gw_proj[r * 48 + c4 * 4]);
    }
    CP_COMMIT;
    CP_WAIT0;
    __syncthreads();

    float accA[12][4], accB[12][4];
    #pragma unroll
    for (int ni = 0; ni < 12; ni++) {
        accA[ni][0] = accA[ni][1] = accA[ni][2] = accA[ni][3] = 0.f;
        accB[ni][0] = accB[ni][1] = accB[ni][2] = accB[ni][3] = 0.f;
    }
    bgemm_dual<12, 6>(O_s, Ws, accA, accB, tm, l);

    #pragma unroll
    for (int ni = 0; ni < 12; ni++) {
        int cn = ni * 8 + 2 * tg;
        float b0v = proj_b[cn], b1v = proj_b[cn + 1];
        #pragma unroll
        for (int p = 0; p < 2; p++) {
            int rowA = tm + p * 8 + g;
            int rowB = tm + 16 + p * 8 + g;
            float* tA = &g_t[((size_t)w * NTOK + rowA) * CH + cn];
            float* tB = &g_t[((size_t)w * NTOK + rowB) * CH + cn];
            float2 pA = *(float2*)tA, pB = *(float2*)tB;
            pA.x += accA[ni][2*p] + b0v;  pA.y += accA[ni][2*p+1] + b1v;
            pB.x += accB[ni][2*p] + b0v;  pB.y += accB[ni][2*p+1] + b1v;
            *(float2*)tA = pA; *(float2*)tB = pB;
        }
    }
}

// ---------------------------------------------------------------------------
// K3: fused MLP: LN2 + fc1 + tanh-GELU(regs) + fc2 + residual, 128 tokens/CTA
// ---------------------------------------------------------------------------
__global__ __launch_bounds__(256, 2) void mlp_kernel(const float* __restrict__ ln_g,
                                                     const float* __restrict__ ln_b,
                                                     const float* __restrict__ fc1_b,
                                                     const float* __restrict__ fc2_b,
                                                     float* __restrict__ out) {
    extern __shared__ uint32_t sm[];
    uint32_t* As = sm;                                  // 6656
    uint32_t* W1[2] = {sm + 6656,              sm + 6656 + 4992};
    uint32_t* W2[2] = {sm + 6656 + 2 * 4992,   sm + 6656 + 3 * 4992};
    int bw = blockIdx.x, w = bw >> 1, half = bw & 1;
    int t = threadIdx.x, l = t & 31, wid = t >> 5, tm = wid * 16;
    int g = l >> 2, tg = l & 3;

    for (int idx = t; idx < 96 * 12; idx += 256) {
        int r = idx / 12, c4 = idx % 12;
        cp_async16(&W1[0][r * LDW + c4 * 4], &gw_fc1[r * 48 + c4 * 4]);
        cp_async16(&W2[0][r * LDW + c4 * 4], &gw_fc2[r * 192 + c4 * 4]);
    }
    CP_COMMIT;

    if (t < 128) {
        int tok = half * 128 + t;
        const float4* tp = (const float4*)(g_t + ((size_t)w * NTOK + tok) * CH);
        float row[96];
        float sum = 0.f, sq = 0.f;
        #pragma unroll
        for (int c4 = 0; c4 < 24; c4++) {
            float4 v = tp[c4];
            row[4*c4] = v.x; row[4*c4+1] = v.y; row[4*c4+2] = v.z; row[4*c4+3] = v.w;
            sum += v.x + v.y + v.z + v.w;
            sq  += v.x*v.x + v.y*v.y + v.z*v.z + v.w*v.w;
        }
        float mean = sum * (1.f / CH);
        float rstd = rsqrtf(sq * (1.f / CH) - mean * mean + 1e-5f);
        #pragma unroll
        for (int p = 0; p < 48; p++) {
            float n0 = (row[2*p]   - mean) * rstd * __ldg(ln_g + 2*p)   + __ldg(ln_b + 2*p);
            float n1 = (row[2*p+1] - mean) * rstd * __ldg(ln_g + 2*p+1) + __ldg(ln_b + 2*p+1);
            As[t * LDW + p] = pk(n0, n1);
        }
    }

    float acc2[12][4];
    #pragma unroll
    for (int ni = 0; ni < 12; ni++)
        acc2[ni][0] = acc2[ni][1] = acc2[ni][2] = acc2[ni][3] = 0.f;

    for (int c = 0; c < 4; c++) {
        int cur = c & 1, nxt = cur ^ 1;
        CP_WAIT0;
        __syncthreads();
        if (c < 3) {
            for (int idx = t; idx < 96 * 12; idx += 256) {
                int r = idx / 12, c4 = idx % 12;
                cp_async16(&W1[nxt][r * LDW + c4 * 4], &gw_fc1[((c + 1) * 96 + r) * 48 + c4 * 4]);
                cp_async16(&W2[nxt][r * LDW + c4 * 4], &gw_fc2[r * 192 + (c + 1) * 48 + c4 * 4]);
            }
            CP_COMMIT;
        }

        float acc1[12][4];
        #pragma unroll
        for (int ni = 0; ni < 12; ni++)
            acc1[ni][0] = acc1[ni][1] = acc1[ni][2] = acc1[ni][3] = 0.f;
        bgemm<12, 6>(As, W1[cur], acc1, tm, l);

        uint32_t pa[6][4];
        #pragma unroll
        for (int ni = 0; ni < 12; ni++) {
            int cn = ni * 8 + 2 * tg;
            float b0v = fc1_b[c * CH + cn], b1v = fc1_b[c * CH + cn + 1];
            acc1[ni][0] = gelu_f(acc1[ni][0] + b0v);
            acc1[ni][1] = gelu_f(acc1[ni][1] + b1v);
            acc1[ni][2] = gelu_f(acc1[ni][2] + b0v);
            acc1[ni][3] = gelu_f(acc1[ni][3] + b1v);
        }
        #pragma unroll
        for (int ks = 0; ks < 6; ks++) {
            pa[ks][0] = pk(acc1[2*ks][0],   acc1[2*ks][1]);
            pa[ks][1] = pk(acc1[2*ks][2],   acc1[2*ks][3]);
            pa[ks][2] = pk(acc1[2*ks+1][0], acc1[2*ks+1][1]);
            pa[ks][3] = pk(acc1[2*ks+1][2], acc1[2*ks+1][3]);
        }
        bgemm_ra<12, 6>(pa, W2[cur], acc2, l);
    }

    #pragma unroll
    for (int ni = 0; ni < 12; ni++) {
        int cn = ni * 8 + 2 * tg;
        float b0v = fc2_b[cn], b1v = fc2_b[cn + 1];
        #pragma unroll
        for (int p = 0; p < 2; p++) {
            int row = half * 128 + tm + p * 8 + g;
            const float2 tr = *(const float2*)&g_t[((size_t)w * NTOK + row) * CH + cn];
            float2 v = make_float2(acc2[ni][2*p]   + b0v + tr.x,
                                   acc2[ni][2*p+1] + b1v + tr.y);
            *(float2*)&out[((size_t)w * NTOK + row) * CH + cn] = v;
        }
    }
}

// ---------------------------------------------------------------------------
extern "C" void kernel_launch(void* const* d_in, const int* in_sizes, int n_in,
                              void* d_out, int out_size) {
    (void)in_sizes; (void)n_in; (void)out_size;
    const float* x      = (const float*)d_in[0];
    const float* qkv_w  = (const float*)d_in[1];
    const float* qkv_b  = (const float*)d_in[2];
    const float* proj_w = (const float*)d_in[3];
    const float* proj_b = (const float*)d_in[4];
    const float* btab   = (const float*)d_in[5];
    const float* ln1_g  = (const float*)d_in[6];
    const float* ln1_b  = (const float*)d_in[7];
    const float* ln2_g  = (const float*)d_in[8];
    const float* ln2_b  = (const float*)d_in[9];
    const float* fc1_w  = (const float*)d_in[10];
    const float* fc1_b  = (const float*)d_in[11];
    const float* fc2_w  = (const float*)d_in[12];
    const float* fc2_b  = (const float*)d_in[13];
    float* out = (float*)d_out;

    const int smem_qkv  = (128 * LDW + 2 * 96 * LDW) * 4;    // 66560 B
    const int smem_attn = (13312 + 5120 + 5120) * 4;         // 94208 B
    const int smem_mlp  = (6656 + 4 * 4992) * 4;             // 106496 B
    cudaFuncSetAttribute(qkv_kernel,  cudaFuncAttributeMaxDynamicSharedMemorySize, smem_qkv);
    cudaFuncSetAttribute(attn_kernel, cudaFuncAttributeMaxDynamicSharedMemorySize, smem_attn);
    cudaFuncSetAttribute(mlp_kernel,  cudaFuncAttributeMaxDynamicSharedMemorySize, smem_mlp);

    prep_kernel<<<408, 256>>>(qkv_w, proj_w, fc1_w, fc2_w, btab);
    qkv_kernel<<<NWIN * 2, 256, smem_qkv>>>(x, qkv_b, ln1_g, ln1_b);
    attn_kernel<<<NWIN, 256, smem_attn>>>(proj_b);
    mlp_kernel<<<NWIN * 2, 256, smem_mlp>>>(ln2_g, ln2_b, fc1_b, fc2_b, out);
}

// round 16
// speedup vs baseline: 1.3697x; 1.1282x over previous
#include <cuda_runtime.h>
#include <cuda_bf16.h>
#include <math.h>
#include <stdint.h>

#define NWIN 512
#define NTOK 256
#define CH   96
#define NH   3
#define HD   32
#define HID  384
#define LDW  52    // stride (uint32) for 48-word operand rows (GEMM A/B, O_s)
#define LDV  20    // stride (uint32) for 16-word rows (K_s, V_s)
#define LOG2E 1.4426950408889634f

// Scratch (device globals)
__device__ float         g_t[(size_t)NWIN * NTOK * CH];       // residual fp32 [w][t][c]
__device__ __nv_bfloat16 g_q[(size_t)NWIN * NH * NTOK * HD];  // [t][d], pre-scaled by hd^-.5*log2e
__device__ __nv_bfloat16 g_k[(size_t)NWIN * NH * NTOK * HD];
__device__ __nv_bfloat16 g_v[(size_t)NWIN * NH * NTOK * HD];
// bias in per-thread C-fragment layout, bf16x2, *log2e
__device__ uint32_t g_biasb[3 * 16 * 4 * 32 * 16];
// weights as bf16x2 pairs
__device__ uint32_t gw_qkv[288 * 48];
__device__ uint32_t gw_proj[96 * 48];
__device__ uint32_t gw_fc1[384 * 48];
__device__ uint32_t gw_fc2[96 * 192];

// ---------------------------------------------------------------------------
__device__ __forceinline__ void cp_async16(void* s, const void* g) {
    uint32_t sa = (uint32_t)__cvta_generic_to_shared(s);
    asm volatile("cp.async.cg.shared.global [%0], [%1], 16;" :: "r"(sa), "l"(g));
}
#define CP_COMMIT asm volatile("cp.async.commit_group;")
#define CP_WAIT0  asm volatile("cp.async.wait_group 0;")

__device__ __forceinline__ uint32_t s2u(const void* p) {
    return (uint32_t)__cvta_generic_to_shared(p);
}
__device__ __forceinline__ uint32_t pk(float a, float b) {
    __nv_bfloat162 h = __floats2bfloat162_rn(a, b);
    return *(uint32_t*)&h;
}
__device__ __forceinline__ float2 upk(uint32_t u) {
    return __bfloat1622float2(*(const __nv_bfloat162*)&u);
}
__device__ __forceinline__ float ex2(float x) {
    float y;
    asm("ex2.approx.ftz.f32 %0, %1;" : "=f"(y) : "f"(x));
    return y;
}
// tanh-form GELU via HW tanh.approx (1 MUFU + ~4 FFMA per value)
__device__ __forceinline__ float gelu_f(float v) {
    float u = v * (0.7978845608f + 0.0356774081f * v * v);
    float th;
    asm("tanh.approx.f32 %0, %1;" : "=f"(th) : "f"(u));
    return 0.5f * v * (1.f + th);
}
__device__ __forceinline__ void bmma(float* c, const uint32_t* a, uint32_t b0, uint32_t b1) {
    asm("mma.sync.aligned.m16n8k16.row.col.f32.bf16.bf16.f32 "
        "{%0,%1,%2,%3},{%4,%5,%6,%7},{%8,%9},{%0,%1,%2,%3};"
        : "+f"(c[0]), "+f"(c[1]), "+f"(c[2]), "+f"(c[3])
        : "r"(a[0]), "r"(a[1]), "r"(a[2]), "r"(a[3]), "r"(b0), "r"(b1));
}
__device__ __forceinline__ void ldsm4(uint32_t* r, uint32_t a) {
    asm volatile("ldmatrix.sync.aligned.m8n8.x4.shared.b16 {%0,%1,%2,%3},[%4];"
        : "=r"(r[0]), "=r"(r[1]), "=r"(r[2]), "=r"(r[3]) : "r"(a));
}
__device__ __forceinline__ void ldsm4t(uint32_t* r, uint32_t a) {
    asm volatile("ldmatrix.sync.aligned.m8n8.x4.trans.shared.b16 {%0,%1,%2,%3},[%4];"
        : "=r"(r[0]), "=r"(r[1]), "=r"(r[2]), "=r"(r[3]) : "r"(a));
}

// 16 rows x NT*8 cols over KS*16 k; A from smem (stride LDW), B from smem.
template <int NT, int KS>
__device__ __forceinline__ void bgemm(const uint32_t* __restrict__ As,
                                      const uint32_t* __restrict__ Ws,
                                      float acc[NT][4], int tm, int l) {
    uint32_t aAddr = s2u(As) + ((tm + (l & 7) + ((l >> 3) & 1) * 8) * LDW + ((l >> 4) & 1) * 4) * 4;
    uint32_t bAddr = s2u(Ws) + (((l & 7) + ((l >> 4) & 1) * 8) * LDW + ((l >> 3) & 1) * 4) * 4;
    #pragma unroll
    for (int ks = 0; ks < KS; ks++) {
        uint32_t a[4];
        ldsm4(a, aAddr + ks * 32);
        #pragma unroll
        for (int nq = 0; nq < NT / 2; nq++) {
            uint32_t b[4];
            ldsm4(b, bAddr + (nq * 16 * LDW) * 4 + ks * 32);
            bmma(acc[2 * nq],     a, b[0], b[1]);
            bmma(acc[2 * nq + 1], a, b[2], b[3]);
        }
    }
}

// 32 rows (two 16-row tiles sharing B fragments) x NT*8 cols over KS*16 k.
template <int NT, int KS>
__device__ __forceinline__ void bgemm_dual(const uint32_t* __restrict__ As,
                                           const uint32_t* __restrict__ Ws,
                                           float accA[NT][4], float accB[NT][4],
                                           int tm, int l) {
    uint32_t aAddr = s2u(As) + ((tm + (l & 7) + ((l >> 3) & 1) * 8) * LDW + ((l >> 4) & 1) * 4) * 4;
    uint32_t bAddr = s2u(Ws) + (((l & 7) + ((l >> 4) & 1) * 8) * LDW + ((l >> 3) & 1) * 4) * 4;
    #pragma unroll
    for (int ks = 0; ks < KS; ks++) {
        uint32_t a0[4], a1[4];
        ldsm4(a0, aAddr + ks * 32);
        ldsm4(a1, aAddr + (16 * LDW) * 4 + ks * 32);
        #pragma unroll
        for (int nq = 0; nq < NT / 2; nq++) {
            uint32_t b[4];
            ldsm4(b, bAddr + (nq * 16 * LDW) * 4 + ks * 32);
            bmma(accA[2 * nq],     a0, b[0], b[1]);
            bmma(accA[2 * nq + 1], a0, b[2], b[3]);
            bmma(accB[2 * nq],     a1, b[0], b[1]);
            bmma(accB[2 * nq + 1], a1, b[2], b[3]);
        }
    }
}

// Same, but A fragments already in registers (pa[ks][4]).
template <int NT, int KS>
__device__ __forceinline__ void bgemm_ra(const uint32_t pa[][4],
                                         const uint32_t* __restrict__ Ws,
                                         float acc[NT][4], int l) {
    uint32_t bAddr = s2u(Ws) + (((l & 7) + ((l >> 4) & 1) * 8) * LDW + ((l >> 3) & 1) * 4) * 4;
    #pragma unroll
    for (int ks = 0; ks < KS; ks++) {
        #pragma unroll
        for (int nq = 0; nq < NT / 2; nq++) {
            uint32_t b[4];
            ldsm4(b, bAddr + (nq * 16 * LDW) * 4 + ks * 32);
            bmma(acc[2 * nq],     pa[ks], b[0], b[1]);
            bmma(acc[2 * nq + 1], pa[ks], b[2], b[3]);
        }
    }
}

// ---------------------------------------------------------------------------
// K0: fused prep (weights -> bf16x2) + bias gather (fragment layout)
// ---------------------------------------------------------------------------
__global__ void prep_kernel(const float* __restrict__ qkv_w, const float* __restrict__ proj_w,
                            const float* __restrict__ fc1_w, const float* __restrict__ fc2_w,
                            const float* __restrict__ bias_table) {
    if (blockIdx.x < 216) {
        int i = blockIdx.x * 256 + threadIdx.x;
        if (i < 13824) {
            int r = i / 48, p = i % 48;
            gw_qkv[i] = pk(qkv_w[r * 96 + 2 * p], qkv_w[r * 96 + 2 * p + 1]);
            return;
        }
        i -= 13824;
        if (i < 4608) {
            int r = i / 48, p = i % 48;
            gw_proj[i] = pk(proj_w[r * 96 + 2 * p], proj_w[r * 96 + 2 * p + 1]);
            return;
        }
        i -= 4608;
        if (i < 18432) {
            int r = i / 48, p = i % 48;
            gw_fc1[i] = pk(fc1_w[r * 96 + 2 * p], fc1_w[r * 96 + 2 * p + 1]);
            return;
        }
        i -= 18432;
        if (i < 18432) {
            int r = i / 192, p = i % 192;
            gw_fc2[i] = pk(fc2_w[r * 384 + 2 * p], fc2_w[r * 384 + 2 * p + 1]);
        }
        return;
    }
    int blk = blockIdx.x - 216;
    int j = blk & 3, rb = (blk >> 2) & 15, h = blk >> 6;
    int t = threadIdx.x;
    uint32_t* dst = g_biasb + blk * 512;
    #pragma unroll
    for (int q = 0; q < 2; q++) {
        int o = t * 2 + q;
        int l = o >> 4, wd = o & 15;
        int ni = wd >> 1, pp = wd & 1;
        float bv[2];
        #pragma unroll
        for (int e = 0; e < 2; e++) {
            int c = pp * 2 + e;
            int row = rb * 16 + (l >> 2) + ((c >> 1) << 3);
            int col = j * 64 + ni * 8 + 2 * (l & 3) + (c & 1);
            int dy = (col >> 4) - (row >> 4);
            int dx = (col & 15) - (row & 15);
            bv[e] = bias_table[((dy + 15) * 31 + (dx + 15)) * NH + h] * LOG2E;
        }
        dst[o] = pk(bv[0], bv[1]);
    }
}

// ---------------------------------------------------------------------------
// K1: window partition + LN1 + QKV GEMM, 128 tokens/CTA.
// x gather split across all 256 threads (48 ch each); LN via smem exchange.
// ---------------------------------------------------------------------------
__global__ __launch_bounds__(256, 2) void qkv_kernel(const float* __restrict__ x,
                                                     const float* __restrict__ qkv_b,
                                                     const float* __restrict__ ln_g,
                                                     const float* __restrict__ ln_b) {
    extern __shared__ uint32_t sm[];
    uint32_t* As  = sm;               // [128][LDW]
    uint32_t* Wb0 = sm + 128 * LDW;
    uint32_t* Wb1 = Wb0 + 96 * LDW;
    float2* red   = (float2*)(Wb1 + 96 * LDW);  // [256] partial (sum, sq)
    int bw = blockIdx.x, w = bw >> 1, half = bw & 1;
    int t = threadIdx.x, l = t & 31, wid = t >> 5, tm = wid * 16;
    int g = l >> 2, tg = l & 3;
    int b = w >> 8, hb = (w >> 4) & 15, wb = w & 15;

    for (int idx = t; idx < 96 * 12; idx += 256) {
        int r = idx / 12, c4 = idx % 12;
        cp_async16(&Wb0[r * LDW + c4 * 4], &gw_qkv[r * 48 + c4 * 4]);
    }
    CP_COMMIT;

    // --- gather 48 channels per thread (all 256 threads active) ---
    int tok = t & 127, hseg = t >> 7;          // hseg: channel half
    int gtok = half * 128 + tok;
    {
        int d = gtok >> 6, ii = (gtok >> 3) & 7, jj = gtok & 7;
        const float* xp = x + ((size_t)(b * CH * 4 + hseg * 48 * 4) + d) * 16384
                            + (hb * 8 + ii) * 128 + (wb * 8 + jj);
        float row[48];
        float sum = 0.f, sq = 0.f;
        #pragma unroll 4
        for (int c = 0; c < 48; c++) {
            float v = xp[(size_t)c * 65536];
            sum += v; sq += v * v;
            row[c] = v;
        }
        // residual store (48 contiguous floats)
        float* gt = g_t + ((size_t)w * NTOK + gtok) * CH + hseg * 48;
        #pragma unroll
        for (int c4 = 0; c4 < 12; c4++)
            *(float4*)&gt[4 * c4] = make_float4(row[4*c4], row[4*c4+1], row[4*c4+2], row[4*c4+3]);
        red[t] = make_float2(sum, sq);
        __syncthreads();
        float2 p0 = red[tok], p1 = red[tok + 128];
        float mean = (p0.x + p1.x) * (1.f / CH);
        float rstd = rsqrtf((p0.y + p1.y) * (1.f / CH) - mean * mean + 1e-5f);
        #pragma unroll
        for (int p = 0; p < 24; p++) {
            int cp = hseg * 24 + p;           // global pair index
            float n0 = (row[2*p]   - mean) * rstd * __ldg(ln_g + 2*cp)   + __ldg(ln_b + 2*cp);
            float n1 = (row[2*p+1] - mean) * rstd * __ldg(ln_g + 2*cp+1) + __ldg(ln_b + 2*cp+1);
            As[tok * LDW + cp] = pk(n0, n1);
        }
    }

    const float QS = 0.17677669529663687f * LOG2E;
    for (int chunk = 0; chunk < 3; chunk++) {
        uint32_t* Wc = (chunk & 1) ? Wb1 : Wb0;
        uint32_t* Wn = (chunk & 1) ? Wb0 : Wb1;
        CP_WAIT0;
        __syncthreads();
        if (chunk < 2) {
            for (int idx = t; idx < 96 * 12; idx += 256) {
                int r = idx / 12, c4 = idx % 12;
                cp_async16(&Wn[r * LDW + c4 * 4], &gw_qkv[((chunk + 1) * 96 + r) * 48 + c4 * 4]);
            }
            CP_COMMIT;
        }
        float acc[12][4];
        #pragma unroll
        for (int ni = 0; ni < 12; ni++)
            acc[ni][0] = acc[ni][1] = acc[ni][2] = acc[ni][3] = 0.f;
        bgemm<12, 6>(As, Wc, acc, tm, l);

        #pragma unroll
        for (int ni = 0; ni < 12; ni++) {
            int cn = ni * 8 + 2 * tg;
            int h = cn >> 5, dd = cn & 31;
            float b0v = qkv_b[chunk * CH + cn], b1v = qkv_b[chunk * CH + cn + 1];
            size_t base = ((size_t)(w * NH + h)) * NTOK;
            #pragma unroll
            for (int p = 0; p < 2; p++) {
                int row = half * 128 + tm + p * 8 + g;
                float v0 = acc[ni][2*p]   + b0v;
                float v1 = acc[ni][2*p+1] + b1v;
                uint32_t* dst = (chunk == 0) ? (uint32_t*)g_q
                              : (chunk == 1) ? (uint32_t*)g_k : (uint32_t*)g_v;
                float sc = (chunk == 0) ? QS : 1.f;
                dst[(base + row) * 16 + (dd >> 1)] = pk(v0 * sc, v1 * sc);
            }
        }
    }
}

// ---------------------------------------------------------------------------
// K2: fused attention (3 heads) + proj + residual; ONE CTA per window.
// ---------------------------------------------------------------------------
__global__ __launch_bounds__(256, 2) void attn_kernel(const float* __restrict__ proj_b) {
    extern __shared__ uint32_t smu[];
    uint32_t* O_s = smu;              // 13312
    uint32_t* K_s = smu + 13312;      // 5120
    uint32_t* V_s = smu + 18432;      // 5120
    uint32_t* Ws  = smu + 13312;      // overlay (proj)
    int w = blockIdx.x;
    int t = threadIdx.x, l = t & 31, wid = t >> 5, tm = wid * 32;
    int g = l >> 2, tg = l & 3;

    uint32_t kAddr = s2u(K_s) + (((l & 7) + ((l >> 4) & 1) * 8) * LDV + ((l >> 3) & 1) * 4) * 4;
    uint32_t vAddr = s2u(V_s) + (((l & 7) + ((l >> 3) & 1) * 8) * LDV + ((l >> 4) & 1) * 4) * 4;

    for (int h = 0; h < NH; h++) {
        size_t hbo = ((size_t)(w * NH + h)) * NTOK * HD;

        __syncthreads();
        for (int idx = t; idx < 2048; idx += 256) {
            int m = (idx & 1023) >> 2, c = idx & 3;
            const __nv_bfloat16* src = (idx < 1024) ? g_k : g_v;
            uint32_t* dst = (idx < 1024) ? K_s : V_s;
            cp_async16(&dst[m * LDV + c * 4], &src[hbo + m * 32 + c * 8]);
        }
        CP_COMMIT;

        uint32_t qa[2][2][4];
        {
            const uint32_t* qp = (const uint32_t*)(g_q + hbo);
            #pragma unroll
            for (int mi = 0; mi < 2; mi++) {
                int qrow = tm + mi * 16 + g;
                #pragma unroll
                for (int ks = 0; ks < 2; ks++) {
                    qa[mi][ks][0] = qp[qrow * 16 + 8 * ks + tg];
                    qa[mi][ks][1] = qp[(qrow + 8) * 16 + 8 * ks + tg];
                    qa[mi][ks][2] = qp[qrow * 16 + 8 * ks + tg + 4];
                    qa[mi][ks][3] = qp[(qrow + 8) * 16 + 8 * ks + tg + 4];
                }
            }
        }
        CP_WAIT0;
        __syncthreads();

        float l_r[2][2] = {{0.f, 0.f}, {0.f, 0.f}};
        float o[2][4][4];
        #pragma unroll
        for (int mi = 0; mi < 2; mi++)
            #pragma unroll
            for (int ni = 0; ni < 4; ni++)
                o[mi][ni][0] = o[mi][ni][1] = o[mi][ni][2] = o[mi][ni][3] = 0.f;

        for (int j = 0; j < 4; j++) {
            float s[2][8][4];
            #pragma unroll
            for (int mi = 0; mi < 2; mi++) {
                const uint4* bf = (const uint4*)(g_biasb +
                    (((h * 16 + wid * 2 + mi) * 4 + j) << 9) + l * 16);
                uint4 u0 = bf[0], u1 = bf[1], u2 = bf[2], u3 = bf[3];
                uint32_t wds[16] = {u0.x, u0.y, u0.z, u0.w, u1.x, u1.y, u1.z, u1.w,
                                    u2.x, u2.y, u2.z, u2.w, u3.x, u3.y, u3.z, u3.w};
                #pragma unroll
                for (int ni = 0; ni < 8; ni++) {
                    float2 a = upk(wds[2 * ni]);
                    float2 b = upk(wds[2 * ni + 1]);
                    s[mi][ni][0] = a.x; s[mi][ni][1] = a.y;
                    s[mi][ni][2] = b.x; s[mi][ni][3] = b.y;
                }
            }
            #pragma unroll
            for (int np = 0; np < 4; np++)
                #pragma unroll
                for (int ks = 0; ks < 2; ks++) {
                    uint32_t bq[4];
                    ldsm4(bq, kAddr + ((j * 64 + np * 16) * LDV + ks * 8) * 4);
                    #pragma unroll
                    for (int mi = 0; mi < 2; mi++) {
                        bmma(s[mi][2 * np],     qa[mi][ks], bq[0], bq[1]);
                        bmma(s[mi][2 * np + 1], qa[mi][ks], bq[2], bq[3]);
                    }
                }
            #pragma unroll
            for (int mi = 0; mi < 2; mi++)
                #pragma unroll
                for (int ni = 0; ni < 8; ni++) {
                    s[mi][ni][0] = ex2(s[mi][ni][0]);
                    s[mi][ni][1] = ex2(s[mi][ni][1]);
                    s[mi][ni][2] = ex2(s[mi][ni][2]);
                    s[mi][ni][3] = ex2(s[mi][ni][3]);
                    l_r[mi][0] += s[mi][ni][0] + s[mi][ni][1];
                    l_r[mi][1] += s[mi][ni][2] + s[mi][ni][3];
                }
            uint32_t pa[2][4][4];
            #pragma unroll
            for (int mi = 0; mi < 2; mi++)
                #pragma unroll
                for (int ks = 0; ks < 4; ks++) {
                    pa[mi][ks][0] = pk(s[mi][2*ks][0],   s[mi][2*ks][1]);
                    pa[mi][ks][1] = pk(s[mi][2*ks][2],   s[mi][2*ks][3]);
                    pa[mi][ks][2] = pk(s[mi][2*ks+1][0], s[mi][2*ks+1][1]);
                    pa[mi][ks][3] = pk(s[mi][2*ks+1][2], s[mi][2*ks+1][3]);
                }
            #pragma unroll
            for (int ks = 0; ks < 4; ks++)
                #pragma unroll
                for (int nq = 0; nq < 2; nq++) {
                    uint32_t bv[4];
                    ldsm4t(bv, vAddr + ((j * 64 + ks * 16) * LDV + nq * 8) * 4);
                    #pragma unroll
                    for (int mi = 0; mi < 2; mi++) {
                        bmma(o[mi][2 * nq],     pa[mi][ks], bv[0], bv[1]);
                        bmma(o[mi][2 * nq + 1], pa[mi][ks], bv[2], bv[3]);
                    }
                }
        }
        #pragma unroll
        for (int mi = 0; mi < 2; mi++)
            #pragma unroll
            for (int p = 0; p < 2; p++) {
                l_r[mi][p] += __shfl_xor_sync(0xffffffffu, l_r[mi][p], 1);
                l_r[mi][p] += __shfl_xor_sync(0xffffffffu, l_r[mi][p], 2);
            }
        #pragma unroll
        for (int mi = 0; mi < 2; mi++) {
            float rinv[2] = {1.f / l_r[mi][0], 1.f / l_r[mi][1]};
            #pragma unroll
            for (int p = 0; p < 2; p++) {
                int rloc = tm + mi * 16 + p * 8 + g;
                #pragma unroll
                for (int ni = 0; ni < 4; ni++)
                    O_s[rloc * LDW + h * 16 + ni * 4 + tg] =
                        pk(o[mi][ni][2*p] * rinv[p], o[mi][ni][2*p+1] * rinv[p]);
            }
        }
    }

    // ---- proj + residual ----
    __syncthreads();
    for (int idx = t; idx < 96 * 12; idx += 256) {
        int r = idx / 12, c4 = idx % 12;
        cp_async16(&Ws[r * LDW + c4 * 4], &gw_proj[r * 48 + c4 * 4]);
    }
    CP_COMMIT;
    CP_WAIT0;
    __syncthreads();

    float accA[12][4], accB[12][4];
    #pragma unroll
    for (int ni = 0; ni < 12; ni++) {
        accA[ni][0] = accA[ni][1] = accA[ni][2] = accA[ni][3] = 0.f;
        accB[ni][0] = accB[ni][1] = accB[ni][2] = accB[ni][3] = 0.f;
    }
    bgemm_dual<12, 6>(O_s, Ws, accA, accB, tm, l);

    #pragma unroll
    for (int ni = 0; ni < 12; ni++) {
        int cn = ni * 8 + 2 * tg;
        float b0v = proj_b[cn], b1v = proj_b[cn + 1];
        #pragma unroll
        for (int p = 0; p < 2; p++) {
            int rowA = tm + p * 8 + g;
            int rowB = tm + 16 + p * 8 + g;
            float* tA = &g_t[((size_t)w * NTOK + rowA) * CH + cn];
            float* tB = &g_t[((size_t)w * NTOK + rowB) * CH + cn];
            float2 pA = *(float2*)tA, pB = *(float2*)tB;
            pA.x += accA[ni][2*p] + b0v;  pA.y += accA[ni][2*p+1] + b1v;
            pB.x += accB[ni][2*p] + b0v;  pB.y += accB[ni][2*p+1] + b1v;
            *(float2*)tA = pA; *(float2*)tB = pB;
        }
    }
}

// ---------------------------------------------------------------------------
// K3: fused MLP: LN2 + fc1 + tanh-GELU(regs) + fc2 + residual, 128 tokens/CTA
// ---------------------------------------------------------------------------
__global__ __launch_bounds__(256, 2) void mlp_kernel(const float* __restrict__ ln_g,
                                                     const float* __restrict__ ln_b,
                                                     const float* __restrict__ fc1_b,
                                                     const float* __restrict__ fc2_b,
                                                     float* __restrict__ out) {
    extern __shared__ uint32_t sm[];
    uint32_t* As = sm;                                  // 6656
    uint32_t* W1[2] = {sm + 6656,              sm + 6656 + 4992};
    uint32_t* W2[2] = {sm + 6656 + 2 * 4992,   sm + 6656 + 3 * 4992};
    int bw = blockIdx.x, w = bw >> 1, half = bw & 1;
    int t = threadIdx.x, l = t & 31, wid = t >> 5, tm = wid * 16;
    int g = l >> 2, tg = l & 3;

    for (int idx = t; idx < 96 * 12; idx += 256) {
        int r = idx / 12, c4 = idx % 12;
        cp_async16(&W1[0][r * LDW + c4 * 4], &gw_fc1[r * 48 + c4 * 4]);
        cp_async16(&W2[0][r * LDW + c4 * 4], &gw_fc2[r * 192 + c4 * 4]);
    }
    CP_COMMIT;

    if (t < 128) {
        int tok = half * 128 + t;
        const float4* tp = (const float4*)(g_t + ((size_t)w * NTOK + tok) * CH);
        float row[96];
        float sum = 0.f, sq = 0.f;
        #pragma unroll
        for (int c4 = 0; c4 < 24; c4++) {
            float4 v = tp[c4];
            row[4*c4] = v.x; row[4*c4+1] = v.y; row[4*c4+2] = v.z; row[4*c4+3] = v.w;
            sum += v.x + v.y + v.z + v.w;
            sq  += v.x*v.x + v.y*v.y + v.z*v.z + v.w*v.w;
        }
        float mean = sum * (1.f / CH);
        float rstd = rsqrtf(sq * (1.f / CH) - mean * mean + 1e-5f);
        #pragma unroll
        for (int p = 0; p < 48; p++) {
            float n0 = (row[2*p]   - mean) * rstd * __ldg(ln_g + 2*p)   + __ldg(ln_b + 2*p);
            float n1 = (row[2*p+1] - mean) * rstd * __ldg(ln_g + 2*p+1) + __ldg(ln_b + 2*p+1);
            As[t * LDW + p] = pk(n0, n1);
        }
    }

    float acc2[12][4];
    #pragma unroll
    for (int ni = 0; ni < 12; ni++)
        acc2[ni][0] = acc2[ni][1] = acc2[ni][2] = acc2[ni][3] = 0.f;

    for (int c = 0; c < 4; c++) {
        int cur = c & 1, nxt = cur ^ 1;
        CP_WAIT0;
        __syncthreads();
        if (c < 3) {
            for (int idx = t; idx < 96 * 12; idx += 256) {
                int r = idx / 12, c4 = idx % 12;
                cp_async16(&W1[nxt][r * LDW + c4 * 4], &gw_fc1[((c + 1) * 96 + r) * 48 + c4 * 4]);
                cp_async16(&W2[nxt][r * LDW + c4 * 4], &gw_fc2[r * 192 + (c + 1) * 48 + c4 * 4]);
            }
            CP_COMMIT;
        }

        float acc1[12][4];
        #pragma unroll
        for (int ni = 0; ni < 12; ni++)
            acc1[ni][0] = acc1[ni][1] = acc1[ni][2] = acc1[ni][3] = 0.f;
        bgemm<12, 6>(As, W1[cur], acc1, tm, l);

        uint32_t pa[6][4];
        #pragma unroll
        for (int ni = 0; ni < 12; ni++) {
            int cn = ni * 8 + 2 * tg;
            float b0v = fc1_b[c * CH + cn], b1v = fc1_b[c * CH + cn + 1];
            acc1[ni][0] = gelu_f(acc1[ni][0] + b0v);
            acc1[ni][1] = gelu_f(acc1[ni][1] + b1v);
            acc1[ni][2] = gelu_f(acc1[ni][2] + b0v);
            acc1[ni][3] = gelu_f(acc1[ni][3] + b1v);
        }
        #pragma unroll
        for (int ks = 0; ks < 6; ks++) {
            pa[ks][0] = pk(acc1[2*ks][0],   acc1[2*ks][1]);
            pa[ks][1] = pk(acc1[2*ks][2],   acc1[2*ks][3]);
            pa[ks][2] = pk(acc1[2*ks+1][0], acc1[2*ks+1][1]);
            pa[ks][3] = pk(acc1[2*ks+1][2], acc1[2*ks+1][3]);
        }
        bgemm_ra<12, 6>(pa, W2[cur], acc2, l);
    }

    #pragma unroll
    for (int ni = 0; ni < 12; ni++) {
        int cn = ni * 8 + 2 * tg;
        float b0v = fc2_b[cn], b1v = fc2_b[cn + 1];
        #pragma unroll
        for (int p = 0; p < 2; p++) {
            int row = half * 128 + tm + p * 8 + g;
            const float2 tr = *(const float2*)&g_t[((size_t)w * NTOK + row) * CH + cn];
            float2 v = make_float2(acc2[ni][2*p]   + b0v + tr.x,
                                   acc2[ni][2*p+1] + b1v + tr.y);
            *(float2*)&out[((size_t)w * NTOK + row) * CH + cn] = v;
        }
    }
}

// ---------------------------------------------------------------------------
extern "C" void kernel_launch(void* const* d_in, const int* in_sizes, int n_in,
                              void* d_out, int out_size) {
    (void)in_sizes; (void)n_in; (void)out_size;
    const float* x      = (const float*)d_in[0];
    const float* qkv_w  = (const float*)d_in[1];
    const float* qkv_b  = (const float*)d_in[2];
    const float* proj_w = (const float*)d_in[3];
    const float* proj_b = (const float*)d_in[4];
    const float* btab   = (const float*)d_in[5];
    const float* ln1_g  = (const float*)d_in[6];
    const float* ln1_b  = (const float*)d_in[7];
    const float* ln2_g  = (const float*)d_in[8];
    const float* ln2_b  = (const float*)d_in[9];
    const float* fc1_w  = (const float*)d_in[10];
    const float* fc1_b  = (const float*)d_in[11];
    const float* fc2_w  = (const float*)d_in[12];
    const float* fc2_b  = (const float*)d_in[13];
    float* out = (float*)d_out;

    const int smem_qkv  = (128 * LDW + 2 * 96 * LDW + 512) * 4;  // 68608 B
    const int smem_attn = (13312 + 5120 + 5120) * 4;             // 94208 B
    const int smem_mlp  = (6656 + 4 * 4992) * 4;                 // 106496 B
    cudaFuncSetAttribute(qkv_kernel,  cudaFuncAttributeMaxDynamicSharedMemorySize, smem_qkv);
    cudaFuncSetAttribute(attn_kernel, cudaFuncAttributeMaxDynamicSharedMemorySize, smem_attn);
    cudaFuncSetAttribute(mlp_kernel,  cudaFuncAttributeMaxDynamicSharedMemorySize, smem_mlp);

    prep_kernel<<<408, 256>>>(qkv_w, proj_w, fc1_w, fc2_w, btab);
    qkv_kernel<<<NWIN * 2, 256, smem_qkv>>>(x, qkv_b, ln1_g, ln1_b);
    attn_kernel<<<NWIN, 256, smem_attn>>>(proj_b);
    mlp_kernel<<<NWIN * 2, 256, smem_mlp>>>(ln2_g, ln2_b, fc1_b, fc2_b, out);
}

// round 17
// speedup vs baseline: 1.3870x; 1.0126x over previous
#include <cuda_runtime.h>
#include <cuda_bf16.h>
#include <math.h>
#include <stdint.h>

#define NWIN 512
#define NTOK 256
#define CH   96
#define NH   3
#define HD   32
#define HID  384
#define LDW  52    // stride (uint32) for 48-word operand rows (GEMM A/B, O_s)
#define LDV  20    // stride (uint32) for 16-word rows (K_s, V_s)
#define LOG2E 1.4426950408889634f

// Scratch (device globals)
__device__ float         g_t[(size_t)NWIN * NTOK * CH];       // residual fp32 [w][t][c]
__device__ __nv_bfloat16 g_q[(size_t)NWIN * NH * NTOK * HD];  // [t][d], pre-scaled by hd^-.5*log2e
__device__ __nv_bfloat16 g_k[(size_t)NWIN * NH * NTOK * HD];
__device__ __nv_bfloat16 g_v[(size_t)NWIN * NH * NTOK * HD];
// bias in per-thread C-fragment layout, bf16x2, *log2e
__device__ uint32_t g_biasb[3 * 16 * 4 * 32 * 16];
// weights as bf16x2 pairs
__device__ uint32_t gw_qkv[288 * 48];
__device__ uint32_t gw_proj[96 * 48];
__device__ uint32_t gw_fc1[384 * 48];
__device__ uint32_t gw_fc2[96 * 192];

// ---------------------------------------------------------------------------
__device__ __forceinline__ void cp_async16(void* s, const void* g) {
    uint32_t sa = (uint32_t)__cvta_generic_to_shared(s);
    asm volatile("cp.async.cg.shared.global [%0], [%1], 16;" :: "r"(sa), "l"(g));
}
#define CP_COMMIT asm volatile("cp.async.commit_group;")
#define CP_WAIT0  asm volatile("cp.async.wait_group 0;")

__device__ __forceinline__ uint32_t s2u(const void* p) {
    return (uint32_t)__cvta_generic_to_shared(p);
}
__device__ __forceinline__ uint32_t pk(float a, float b) {
    __nv_bfloat162 h = __floats2bfloat162_rn(a, b);
    return *(uint32_t*)&h;
}
__device__ __forceinline__ float2 upk(uint32_t u) {
    return __bfloat1622float2(*(const __nv_bfloat162*)&u);
}
__device__ __forceinline__ float ex2(float x) {
    float y;
    asm("ex2.approx.ftz.f32 %0, %1;" : "=f"(y) : "f"(x));
    return y;
}
// tanh-form GELU via HW tanh.approx (1 MUFU + ~4 FFMA per value)
__device__ __forceinline__ float gelu_f(float v) {
    float u = v * (0.7978845608f + 0.0356774081f * v * v);
    float th;
    asm("tanh.approx.f32 %0, %1;" : "=f"(th) : "f"(u));
    return 0.5f * v * (1.f + th);
}
__device__ __forceinline__ void bmma(float* c, const uint32_t* a, uint32_t b0, uint32_t b1) {
    asm("mma.sync.aligned.m16n8k16.row.col.f32.bf16.bf16.f32 "
        "{%0,%1,%2,%3},{%4,%5,%6,%7},{%8,%9},{%0,%1,%2,%3};"
        : "+f"(c[0]), "+f"(c[1]), "+f"(c[2]), "+f"(c[3])
        : "r"(a[0]), "r"(a[1]), "r"(a[2]), "r"(a[3]), "r"(b0), "r"(b1));
}
__device__ __forceinline__ void ldsm4(uint32_t* r, uint32_t a) {
    asm volatile("ldmatrix.sync.aligned.m8n8.x4.shared.b16 {%0,%1,%2,%3},[%4];"
        : "=r"(r[0]), "=r"(r[1]), "=r"(r[2]), "=r"(r[3]) : "r"(a));
}
__device__ __forceinline__ void ldsm4t(uint32_t* r, uint32_t a) {
    asm volatile("ldmatrix.sync.aligned.m8n8.x4.trans.shared.b16 {%0,%1,%2,%3},[%4];"
        : "=r"(r[0]), "=r"(r[1]), "=r"(r[2]), "=r"(r[3]) : "r"(a));
}

// 16 rows x NT*8 cols over KS*16 k; A from smem (stride LDW), B from smem.
template <int NT, int KS>
__device__ __forceinline__ void bgemm(const uint32_t* __restrict__ As,
                                      const uint32_t* __restrict__ Ws,
                                      float acc[NT][4], int tm, int l) {
    uint32_t aAddr = s2u(As) + ((tm + (l & 7) + ((l >> 3) & 1) * 8) * LDW + ((l >> 4) & 1) * 4) * 4;
    uint32_t bAddr = s2u(Ws) + (((l & 7) + ((l >> 4) & 1) * 8) * LDW + ((l >> 3) & 1) * 4) * 4;
    #pragma unroll
    for (int ks = 0; ks < KS; ks++) {
        uint32_t a[4];
        ldsm4(a, aAddr + ks * 32);
        #pragma unroll
        for (int nq = 0; nq < NT / 2; nq++) {
            uint32_t b[4];
            ldsm4(b, bAddr + (nq * 16 * LDW) * 4 + ks * 32);
            bmma(acc[2 * nq],     a, b[0], b[1]);
            bmma(acc[2 * nq + 1], a, b[2], b[3]);
        }
    }
}

// 32 rows (two 16-row tiles sharing B fragments) x NT*8 cols over KS*16 k.
template <int NT, int KS>
__device__ __forceinline__ void bgemm_dual(const uint32_t* __restrict__ As,
                                           const uint32_t* __restrict__ Ws,
                                           float accA[NT][4], float accB[NT][4],
                                           int tm, int l) {
    uint32_t aAddr = s2u(As) + ((tm + (l & 7) + ((l >> 3) & 1) * 8) * LDW + ((l >> 4) & 1) * 4) * 4;
    uint32_t bAddr = s2u(Ws) + (((l & 7) + ((l >> 4) & 1) * 8) * LDW + ((l >> 3) & 1) * 4) * 4;
    #pragma unroll
    for (int ks = 0; ks < KS; ks++) {
        uint32_t a0[4], a1[4];
        ldsm4(a0, aAddr + ks * 32);
        ldsm4(a1, aAddr + (16 * LDW) * 4 + ks * 32);
        #pragma unroll
        for (int nq = 0; nq < NT / 2; nq++) {
            uint32_t b[4];
            ldsm4(b, bAddr + (nq * 16 * LDW) * 4 + ks * 32);
            bmma(accA[2 * nq],     a0, b[0], b[1]);
            bmma(accA[2 * nq + 1], a0, b[2], b[3]);
            bmma(accB[2 * nq],     a1, b[0], b[1]);
            bmma(accB[2 * nq + 1], a1, b[2], b[3]);
        }
    }
}

// Same, but A fragments already in registers (pa[ks][4]).
template <int NT, int KS>
__device__ __forceinline__ void bgemm_ra(const uint32_t pa[][4],
                                         const uint32_t* __restrict__ Ws,
                                         float acc[NT][4], int l) {
    uint32_t bAddr = s2u(Ws) + (((l & 7) + ((l >> 4) & 1) * 8) * LDW + ((l >> 3) & 1) * 4) * 4;
    #pragma unroll
    for (int ks = 0; ks < KS; ks++) {
        #pragma unroll
        for (int nq = 0; nq < NT / 2; nq++) {
            uint32_t b[4];
            ldsm4(b, bAddr + (nq * 16 * LDW) * 4 + ks * 32);
            bmma(acc[2 * nq],     pa[ks], b[0], b[1]);
            bmma(acc[2 * nq + 1], pa[ks], b[2], b[3]);
        }
    }
}

// ---------------------------------------------------------------------------
// K0: fused prep (weights -> bf16x2) + bias gather (fragment layout)
// ---------------------------------------------------------------------------
__global__ void prep_kernel(const float* __restrict__ qkv_w, const float* __restrict__ proj_w,
                            const float* __restrict__ fc1_w, const float* __restrict__ fc2_w,
                            const float* __restrict__ bias_table) {
    if (blockIdx.x < 216) {
        int i = blockIdx.x * 256 + threadIdx.x;
        if (i < 13824) {
            int r = i / 48, p = i % 48;
            gw_qkv[i] = pk(qkv_w[r * 96 + 2 * p], qkv_w[r * 96 + 2 * p + 1]);
            return;
        }
        i -= 13824;
        if (i < 4608) {
            int r = i / 48, p = i % 48;
            gw_proj[i] = pk(proj_w[r * 96 + 2 * p], proj_w[r * 96 + 2 * p + 1]);
            return;
        }
        i -= 4608;
        if (i < 18432) {
            int r = i / 48, p = i % 48;
            gw_fc1[i] = pk(fc1_w[r * 96 + 2 * p], fc1_w[r * 96 + 2 * p + 1]);
            return;
        }
        i -= 18432;
        if (i < 18432) {
            int r = i / 192, p = i % 192;
            gw_fc2[i] = pk(fc2_w[r * 384 + 2 * p], fc2_w[r * 384 + 2 * p + 1]);
        }
        return;
    }
    int blk = blockIdx.x - 216;
    int j = blk & 3, rb = (blk >> 2) & 15, h = blk >> 6;
    int t = threadIdx.x;
    uint32_t* dst = g_biasb + blk * 512;
    #pragma unroll
    for (int q = 0; q < 2; q++) {
        int o = t * 2 + q;
        int l = o >> 4, wd = o & 15;
        int ni = wd >> 1, pp = wd & 1;
        float bv[2];
        #pragma unroll
        for (int e = 0; e < 2; e++) {
            int c = pp * 2 + e;
            int row = rb * 16 + (l >> 2) + ((c >> 1) << 3);
            int col = j * 64 + ni * 8 + 2 * (l & 3) + (c & 1);
            int dy = (col >> 4) - (row >> 4);
            int dx = (col & 15) - (row & 15);
            bv[e] = bias_table[((dy + 15) * 31 + (dx + 15)) * NH + h] * LOG2E;
        }
        dst[o] = pk(bv[0], bv[1]);
    }
}

// ---------------------------------------------------------------------------
// K1: window partition + LN1 + QKV GEMM, 128 tokens/CTA.
// x gather split across all 256 threads (48 ch each); LN via smem exchange.
// ---------------------------------------------------------------------------
__global__ __launch_bounds__(256, 2) void qkv_kernel(const float* __restrict__ x,
                                                     const float* __restrict__ qkv_b,
                                                     const float* __restrict__ ln_g,
                                                     const float* __restrict__ ln_b) {
    extern __shared__ uint32_t sm[];
    uint32_t* As  = sm;               // [128][LDW]
    uint32_t* Wb0 = sm + 128 * LDW;
    uint32_t* Wb1 = Wb0 + 96 * LDW;
    float2* red   = (float2*)(Wb1 + 96 * LDW);  // [256] partial (sum, sq)
    int bw = blockIdx.x, w = bw >> 1, half = bw & 1;
    int t = threadIdx.x, l = t & 31, wid = t >> 5, tm = wid * 16;
    int g = l >> 2, tg = l & 3;
    int b = w >> 8, hb = (w >> 4) & 15, wb = w & 15;

    for (int idx = t; idx < 96 * 12; idx += 256) {
        int r = idx / 12, c4 = idx % 12;
        cp_async16(&Wb0[r * LDW + c4 * 4], &gw_qkv[r * 48 + c4 * 4]);
    }
    CP_COMMIT;

    int tok = t & 127, hseg = t >> 7;
    int gtok = half * 128 + tok;
    {
        int d = gtok >> 6, ii = (gtok >> 3) & 7, jj = gtok & 7;
        const float* xp = x + ((size_t)(b * CH * 4 + hseg * 48 * 4) + d) * 16384
                            + (hb * 8 + ii) * 128 + (wb * 8 + jj);
        float row[48];
        float sum = 0.f, sq = 0.f;
        #pragma unroll 4
        for (int c = 0; c < 48; c++) {
            float v = xp[(size_t)c * 65536];
            sum += v; sq += v * v;
            row[c] = v;
        }
        float* gt = g_t + ((size_t)w * NTOK + gtok) * CH + hseg * 48;
        #pragma unroll
        for (int c4 = 0; c4 < 12; c4++)
            *(float4*)&gt[4 * c4] = make_float4(row[4*c4], row[4*c4+1], row[4*c4+2], row[4*c4+3]);
        red[t] = make_float2(sum, sq);
        __syncthreads();
        float2 p0 = red[tok], p1 = red[tok + 128];
        float mean = (p0.x + p1.x) * (1.f / CH);
        float rstd = rsqrtf((p0.y + p1.y) * (1.f / CH) - mean * mean + 1e-5f);
        #pragma unroll
        for (int p = 0; p < 24; p++) {
            int cp = hseg * 24 + p;
            float n0 = (row[2*p]   - mean) * rstd * __ldg(ln_g + 2*cp)   + __ldg(ln_b + 2*cp);
            float n1 = (row[2*p+1] - mean) * rstd * __ldg(ln_g + 2*cp+1) + __ldg(ln_b + 2*cp+1);
            As[tok * LDW + cp] = pk(n0, n1);
        }
    }

    const float QS = 0.17677669529663687f * LOG2E;
    for (int chunk = 0; chunk < 3; chunk++) {
        uint32_t* Wc = (chunk & 1) ? Wb1 : Wb0;
        uint32_t* Wn = (chunk & 1) ? Wb0 : Wb1;
        CP_WAIT0;
        __syncthreads();
        if (chunk < 2) {
            for (int idx = t; idx < 96 * 12; idx += 256) {
                int r = idx / 12, c4 = idx % 12;
                cp_async16(&Wn[r * LDW + c4 * 4], &gw_qkv[((chunk + 1) * 96 + r) * 48 + c4 * 4]);
            }
            CP_COMMIT;
        }
        float acc[12][4];
        #pragma unroll
        for (int ni = 0; ni < 12; ni++)
            acc[ni][0] = acc[ni][1] = acc[ni][2] = acc[ni][3] = 0.f;
        bgemm<12, 6>(As, Wc, acc, tm, l);

        #pragma unroll
        for (int ni = 0; ni < 12; ni++) {
            int cn = ni * 8 + 2 * tg;
            int h = cn >> 5, dd = cn & 31;
            float b0v = qkv_b[chunk * CH + cn], b1v = qkv_b[chunk * CH + cn + 1];
            size_t base = ((size_t)(w * NH + h)) * NTOK;
            #pragma unroll
            for (int p = 0; p < 2; p++) {
                int row = half * 128 + tm + p * 8 + g;
                float v0 = acc[ni][2*p]   + b0v;
                float v1 = acc[ni][2*p+1] + b1v;
                uint32_t* dst = (chunk == 0) ? (uint32_t*)g_q
                              : (chunk == 1) ? (uint32_t*)g_k : (uint32_t*)g_v;
                float sc = (chunk == 0) ? QS : 1.f;
                dst[(base + row) * 16 + (dd >> 1)] = pk(v0 * sc, v1 * sc);
            }
        }
    }
}

// ---------------------------------------------------------------------------
// K2: fused attention (3 heads) + proj + residual; ONE CTA per window.
// ---------------------------------------------------------------------------
__global__ __launch_bounds__(256, 2) void attn_kernel(const float* __restrict__ proj_b) {
    extern __shared__ uint32_t smu[];
    uint32_t* O_s = smu;              // 13312
    uint32_t* K_s = smu + 13312;      // 5120
    uint32_t* V_s = smu + 18432;      // 5120
    uint32_t* Ws  = smu + 13312;      // overlay (proj)
    int w = blockIdx.x;
    int t = threadIdx.x, l = t & 31, wid = t >> 5, tm = wid * 32;
    int g = l >> 2, tg = l & 3;

    uint32_t kAddr = s2u(K_s) + (((l & 7) + ((l >> 4) & 1) * 8) * LDV + ((l >> 3) & 1) * 4) * 4;
    uint32_t vAddr = s2u(V_s) + (((l & 7) + ((l >> 3) & 1) * 8) * LDV + ((l >> 4) & 1) * 4) * 4;

    for (int h = 0; h < NH; h++) {
        size_t hbo = ((size_t)(w * NH + h)) * NTOK * HD;

        __syncthreads();
        for (int idx = t; idx < 2048; idx += 256) {
            int m = (idx & 1023) >> 2, c = idx & 3;
            const __nv_bfloat16* src = (idx < 1024) ? g_k : g_v;
            uint32_t* dst = (idx < 1024) ? K_s : V_s;
            cp_async16(&dst[m * LDV + c * 4], &src[hbo + m * 32 + c * 8]);
        }
        CP_COMMIT;

        uint32_t qa[2][2][4];
        {
            const uint32_t* qp = (const uint32_t*)(g_q + hbo);
            #pragma unroll
            for (int mi = 0; mi < 2; mi++) {
                int qrow = tm + mi * 16 + g;
                #pragma unroll
                for (int ks = 0; ks < 2; ks++) {
                    qa[mi][ks][0] = qp[qrow * 16 + 8 * ks + tg];
                    qa[mi][ks][1] = qp[(qrow + 8) * 16 + 8 * ks + tg];
                    qa[mi][ks][2] = qp[qrow * 16 + 8 * ks + tg + 4];
                    qa[mi][ks][3] = qp[(qrow + 8) * 16 + 8 * ks + tg + 4];
                }
            }
        }
        CP_WAIT0;
        __syncthreads();

        float l_r[2][2] = {{0.f, 0.f}, {0.f, 0.f}};
        float o[2][4][4];
        #pragma unroll
        for (int mi = 0; mi < 2; mi++)
            #pragma unroll
            for (int ni = 0; ni < 4; ni++)
                o[mi][ni][0] = o[mi][ni][1] = o[mi][ni][2] = o[mi][ni][3] = 0.f;

        for (int j = 0; j < 4; j++) {
            float s[2][8][4];
            #pragma unroll
            for (int mi = 0; mi < 2; mi++) {
                const uint4* bf = (const uint4*)(g_biasb +
                    (((h * 16 + wid * 2 + mi) * 4 + j) << 9) + l * 16);
                uint4 u0 = bf[0], u1 = bf[1], u2 = bf[2], u3 = bf[3];
                uint32_t wds[16] = {u0.x, u0.y, u0.z, u0.w, u1.x, u1.y, u1.z, u1.w,
                                    u2.x, u2.y, u2.z, u2.w, u3.x, u3.y, u3.z, u3.w};
                #pragma unroll
                for (int ni = 0; ni < 8; ni++) {
                    float2 a = upk(wds[2 * ni]);
                    float2 b = upk(wds[2 * ni + 1]);
                    s[mi][ni][0] = a.x; s[mi][ni][1] = a.y;
                    s[mi][ni][2] = b.x; s[mi][ni][3] = b.y;
                }
            }
            #pragma unroll
            for (int np = 0; np < 4; np++)
                #pragma unroll
                for (int ks = 0; ks < 2; ks++) {
                    uint32_t bq[4];
                    ldsm4(bq, kAddr + ((j * 64 + np * 16) * LDV + ks * 8) * 4);
                    #pragma unroll
                    for (int mi = 0; mi < 2; mi++) {
                        bmma(s[mi][2 * np],     qa[mi][ks], bq[0], bq[1]);
                        bmma(s[mi][2 * np + 1], qa[mi][ks], bq[2], bq[3]);
                    }
                }
            #pragma unroll
            for (int mi = 0; mi < 2; mi++)
                #pragma unroll
                for (int ni = 0; ni < 8; ni++) {
                    s[mi][ni][0] = ex2(s[mi][ni][0]);
                    s[mi][ni][1] = ex2(s[mi][ni][1]);
                    s[mi][ni][2] = ex2(s[mi][ni][2]);
                    s[mi][ni][3] = ex2(s[mi][ni][3]);
                    l_r[mi][0] += s[mi][ni][0] + s[mi][ni][1];
                    l_r[mi][1] += s[mi][ni][2] + s[mi][ni][3];
                }
            uint32_t pa[2][4][4];
            #pragma unroll
            for (int mi = 0; mi < 2; mi++)
                #pragma unroll
                for (int ks = 0; ks < 4; ks++) {
                    pa[mi][ks][0] = pk(s[mi][2*ks][0],   s[mi][2*ks][1]);
                    pa[mi][ks][1] = pk(s[mi][2*ks][2],   s[mi][2*ks][3]);
                    pa[mi][ks][2] = pk(s[mi][2*ks+1][0], s[mi][2*ks+1][1]);
                    pa[mi][ks][3] = pk(s[mi][2*ks+1][2], s[mi][2*ks+1][3]);
                }
            #pragma unroll
            for (int ks = 0; ks < 4; ks++)
                #pragma unroll
                for (int nq = 0; nq < 2; nq++) {
                    uint32_t bv[4];
                    ldsm4t(bv, vAddr + ((j * 64 + ks * 16) * LDV + nq * 8) * 4);
                    #pragma unroll
                    for (int mi = 0; mi < 2; mi++) {
                        bmma(o[mi][2 * nq],     pa[mi][ks], bv[0], bv[1]);
                        bmma(o[mi][2 * nq + 1], pa[mi][ks], bv[2], bv[3]);
                    }
                }
        }
        #pragma unroll
        for (int mi = 0; mi < 2; mi++)
            #pragma unroll
            for (int p = 0; p < 2; p++) {
                l_r[mi][p] += __shfl_xor_sync(0xffffffffu, l_r[mi][p], 1);
                l_r[mi][p] += __shfl_xor_sync(0xffffffffu, l_r[mi][p], 2);
            }
        #pragma unroll
        for (int mi = 0; mi < 2; mi++) {
            float rinv[2] = {1.f / l_r[mi][0], 1.f / l_r[mi][1]};
            #pragma unroll
            for (int p = 0; p < 2; p++) {
                int rloc = tm + mi * 16 + p * 8 + g;
                #pragma unroll
                for (int ni = 0; ni < 4; ni++)
                    O_s[rloc * LDW + h * 16 + ni * 4 + tg] =
                        pk(o[mi][ni][2*p] * rinv[p], o[mi][ni][2*p+1] * rinv[p]);
            }
        }
    }

    // ---- proj + residual ----
    __syncthreads();
    for (int idx = t; idx < 96 * 12; idx += 256) {
        int r = idx / 12, c4 = idx % 12;
        cp_async16(&Ws[r * LDW + c4 * 4], &gw_proj[r * 48 + c4 * 4]);
    }
    CP_COMMIT;
    CP_WAIT0;
    __syncthreads();

    float accA[12][4], accB[12][4];
    #pragma unroll
    for (int ni = 0; ni < 12; ni++) {
        accA[ni][0] = accA[ni][1] = accA[ni][2] = accA[ni][3] = 0.f;
        accB[ni][0] = accB[ni][1] = accB[ni][2] = accB[ni][3] = 0.f;
    }
    bgemm_dual<12, 6>(O_s, Ws, accA, accB, tm, l);

    #pragma unroll
    for (int ni = 0; ni < 12; ni++) {
        int cn = ni * 8 + 2 * tg;
        float b0v = proj_b[cn], b1v = proj_b[cn + 1];
        #pragma unroll
        for (int p = 0; p < 2; p++) {
            int rowA = tm + p * 8 + g;
            int rowB = tm + 16 + p * 8 + g;
            float* tA = &g_t[((size_t)w * NTOK + rowA) * CH + cn];
            float* tB = &g_t[((size_t)w * NTOK + rowB) * CH + cn];
            float2 pA = *(float2*)tA, pB = *(float2*)tB;
            pA.x += accA[ni][2*p] + b0v;  pA.y += accA[ni][2*p+1] + b1v;
            pB.x += accB[ni][2*p] + b0v;  pB.y += accB[ni][2*p+1] + b1v;
            *(float2*)tA = pA; *(float2*)tB = pB;
        }
    }
}

// ---------------------------------------------------------------------------
// K3: fused MLP: LN2 + fc1 + tanh-GELU(regs) + fc2 + residual, 128 tokens/CTA.
// g_t load + LN2 split across all 256 threads (48 ch each) w/ smem exchange.
// ---------------------------------------------------------------------------
__global__ __launch_bounds__(256, 2) void mlp_kernel(const float* __restrict__ ln_g,
                                                     const float* __restrict__ ln_b,
                                                     const float* __restrict__ fc1_b,
                                                     const float* __restrict__ fc2_b,
                                                     float* __restrict__ out) {
    extern __shared__ uint32_t sm[];
    uint32_t* As = sm;                                  // 6656
    uint32_t* W1[2] = {sm + 6656,              sm + 6656 + 4992};
    uint32_t* W2[2] = {sm + 6656 + 2 * 4992,   sm + 6656 + 3 * 4992};
    float2* red = (float2*)(sm + 6656 + 4 * 4992);      // [256]
    int bw = blockIdx.x, w = bw >> 1, half = bw & 1;
    int t = threadIdx.x, l = t & 31, wid = t >> 5, tm = wid * 16;
    int g = l >> 2, tg = l & 3;

    for (int idx = t; idx < 96 * 12; idx += 256) {
        int r = idx / 12, c4 = idx % 12;
        cp_async16(&W1[0][r * LDW + c4 * 4], &gw_fc1[r * 48 + c4 * 4]);
        cp_async16(&W2[0][r * LDW + c4 * 4], &gw_fc2[r * 192 + c4 * 4]);
    }
    CP_COMMIT;

    {
        int tok = t & 127, hseg = t >> 7;
        const float4* tp = (const float4*)(g_t + ((size_t)w * NTOK + half * 128 + tok) * CH + hseg * 48);
        float row[48];
        float sum = 0.f, sq = 0.f;
        #pragma unroll
        for (int c4 = 0; c4 < 12; c4++) {
            float4 v = tp[c4];
            row[4*c4] = v.x; row[4*c4+1] = v.y; row[4*c4+2] = v.z; row[4*c4+3] = v.w;
            sum += v.x + v.y + v.z + v.w;
            sq  += v.x*v.x + v.y*v.y + v.z*v.z + v.w*v.w;
        }
        red[t] = make_float2(sum, sq);
        __syncthreads();
        float2 p0 = red[tok], p1 = red[tok + 128];
        float mean = (p0.x + p1.x) * (1.f / CH);
        float rstd = rsqrtf((p0.y + p1.y) * (1.f / CH) - mean * mean + 1e-5f);
        #pragma unroll
        for (int p = 0; p < 24; p++) {
            int cp = hseg * 24 + p;
            float n0 = (row[2*p]   - mean) * rstd * __ldg(ln_g + 2*cp)   + __ldg(ln_b + 2*cp);
            float n1 = (row[2*p+1] - mean) * rstd * __ldg(ln_g + 2*cp+1) + __ldg(ln_b + 2*cp+1);
            As[tok * LDW + cp] = pk(n0, n1);
        }
    }

    float acc2[12][4];
    #pragma unroll
    for (int ni = 0; ni < 12; ni++)
        acc2[ni][0] = acc2[ni][1] = acc2[ni][2] = acc2[ni][3] = 0.f;

    for (int c = 0; c < 4; c++) {
        int cur = c & 1, nxt = cur ^ 1;
        CP_WAIT0;
        __syncthreads();
        if (c < 3) {
            for (int idx = t; idx < 96 * 12; idx += 256) {
                int r = idx / 12, c4 = idx % 12;
                cp_async16(&W1[nxt][r * LDW + c4 * 4], &gw_fc1[((c + 1) * 96 + r) * 48 + c4 * 4]);
                cp_async16(&W2[nxt][r * LDW + c4 * 4], &gw_fc2[r * 192 + (c + 1) * 48 + c4 * 4]);
            }
            CP_COMMIT;
        }

        float acc1[12][4];
        #pragma unroll
        for (int ni = 0; ni < 12; ni++)
            acc1[ni][0] = acc1[ni][1] = acc1[ni][2] = acc1[ni][3] = 0.f;
        bgemm<12, 6>(As, W1[cur], acc1, tm, l);

        uint32_t pa[6][4];
        #pragma unroll
        for (int ni = 0; ni < 12; ni++) {
            int cn = ni * 8 + 2 * tg;
            float b0v = fc1_b[c * CH + cn], b1v = fc1_b[c * CH + cn + 1];
            acc1[ni][0] = gelu_f(acc1[ni][0] + b0v);
            acc1[ni][1] = gelu_f(acc1[ni][1] + b1v);
            acc1[ni][2] = gelu_f(acc1[ni][2] + b0v);
            acc1[ni][3] = gelu_f(acc1[ni][3] + b1v);
        }
        #pragma unroll
        for (int ks = 0; ks < 6; ks++) {
            pa[ks][0] = pk(acc1[2*ks][0],   acc1[2*ks][1]);
            pa[ks][1] = pk(acc1[2*ks][2],   acc1[2*ks][3]);
            pa[ks][2] = pk(acc1[2*ks+1][0], acc1[2*ks+1][1]);
            pa[ks][3] = pk(acc1[2*ks+1][2], acc1[2*ks+1][3]);
        }
        bgemm_ra<12, 6>(pa, W2[cur], acc2, l);
    }

    #pragma unroll
    for (int ni = 0; ni < 12; ni++) {
        int cn = ni * 8 + 2 * tg;
        float b0v = fc2_b[cn], b1v = fc2_b[cn + 1];
        #pragma unroll
        for (int p = 0; p < 2; p++) {
            int row = half * 128 + tm + p * 8 + g;
            const float2 tr = *(const float2*)&g_t[((size_t)w * NTOK + row) * CH + cn];
            float2 v = make_float2(acc2[ni][2*p]   + b0v + tr.x,
                                   acc2[ni][2*p+1] + b1v + tr.y);
            *(float2*)&out[((size_t)w * NTOK + row) * CH + cn] = v;
        }
    }
}

// ---------------------------------------------------------------------------
extern "C" void kernel_launch(void* const* d_in, const int* in_sizes, int n_in,
                              void* d_out, int out_size) {
    (void)in_sizes; (void)n_in; (void)out_size;
    const float* x      = (const float*)d_in[0];
    const float* qkv_w  = (const float*)d_in[1];
    const float* qkv_b  = (const float*)d_in[2];
    const float* proj_w = (const float*)d_in[3];
    const float* proj_b = (const float*)d_in[4];
    const float* btab   = (const float*)d_in[5];
    const float* ln1_g  = (const float*)d_in[6];
    const float* ln1_b  = (const float*)d_in[7];
    const float* ln2_g  = (const float*)d_in[8];
    const float* ln2_b  = (const float*)d_in[9];
    const float* fc1_w  = (const float*)d_in[10];
    const float* fc1_b  = (const float*)d_in[11];
    const float* fc2_w  = (const float*)d_in[12];
    const float* fc2_b  = (const float*)d_in[13];
    float* out = (float*)d_out;

    const int smem_qkv  = (128 * LDW + 2 * 96 * LDW + 512) * 4;  // 68608 B
    const int smem_attn = (13312 + 5120 + 5120) * 4;             // 94208 B
    const int smem_mlp  = (6656 + 4 * 4992 + 512) * 4;           // 108544 B
    cudaFuncSetAttribute(qkv_kernel,  cudaFuncAttributeMaxDynamicSharedMemorySize, smem_qkv);
    cudaFuncSetAttribute(attn_kernel, cudaFuncAttributeMaxDynamicSharedMemorySize, smem_attn);
    cudaFuncSetAttribute(mlp_kernel,  cudaFuncAttributeMaxDynamicSharedMemorySize, smem_mlp);

    prep_kernel<<<408, 256>>>(qkv_w, proj_w, fc1_w, fc2_w, btab);
    qkv_kernel<<<NWIN * 2, 256, smem_qkv>>>(x, qkv_b, ln1_g, ln1_b);
    attn_kernel<<<NWIN, 256, smem_attn>>>(proj_b);
    mlp_kernel<<<NWIN * 2, 256, smem_mlp>>>(ln2_g, ln2_b, fc1_b, fc2_b, out);
}